// round 1
// baseline (speedup 1.0000x reference)
#include <cuda_runtime.h>
#include <math.h>

#define BB 8
#define SS 2048
#define DD 512
#define FF_ 2048
#define HH 8
#define DH 64
#define TOPQ 39
#define NROWS (BB*SS)   /* 16384 */

// ---------------- static scratch (no runtime allocation) ----------------
__device__ float g_xn  [NROWS*DD];        // layernorm1 output
__device__ float g_x2  [NROWS*DD];        // x + attn_out
__device__ float g_xn2 [NROWS*DD];        // layernorm2 output
__device__ float g_kv  [NROWS*2*DD];      // [n,0:512]=k  [n,512:1024]=v
__device__ float g_h1  [NROWS*FF_];       // gelu(x@w1^T+b1)
__device__ float g_cs  [BB*DD];           // column sums of xn per batch
__device__ float g_sp  [BB*SS];           // sparsity measure
__device__ int   g_tidx[BB*TOPQ];         // top-q indices
__device__ float g_qs  [BB*TOPQ*DD];      // projected sparse queries
__device__ float g_ctx [BB*TOPQ*DD];      // attention context
__device__ float g_aout[BB*TOPQ*DD];      // out-projected context

// ---------------- layernorm (one row per block, 128 threads) ----------------
__global__ __launch_bounds__(128) void ln_kernel(const float* __restrict__ x,
        const float* __restrict__ g, const float* __restrict__ bb,
        float* __restrict__ out)
{
    int row = blockIdx.x;
    int t   = threadIdx.x;
    float4 v = ((const float4*)x)[(size_t)row*(DD/4) + t];
    float s = v.x + v.y + v.z + v.w;
    __shared__ float red[4];
    #pragma unroll
    for (int o = 16; o > 0; o >>= 1) s += __shfl_down_sync(0xffffffffu, s, o);
    if ((t & 31) == 0) red[t >> 5] = s;
    __syncthreads();
    float mean = (red[0] + red[1] + red[2] + red[3]) * (1.0f/DD);
    __syncthreads();
    float dx = v.x - mean, dy = v.y - mean, dz = v.z - mean, dw = v.w - mean;
    float q = dx*dx + dy*dy + dz*dz + dw*dw;
    #pragma unroll
    for (int o = 16; o > 0; o >>= 1) q += __shfl_down_sync(0xffffffffu, q, o);
    if ((t & 31) == 0) red[t >> 5] = q;
    __syncthreads();
    float var = (red[0] + red[1] + red[2] + red[3]) * (1.0f/DD);
    float inv = rsqrtf(var + 1e-5f);
    float4 gg = ((const float4*)g)[t];
    float4 bv = ((const float4*)bb)[t];
    float4 o4 = make_float4(dx*inv*gg.x + bv.x, dy*inv*gg.y + bv.y,
                            dz*inv*gg.z + bv.z, dw*inv*gg.w + bv.w);
    ((float4*)out)[(size_t)row*(DD/4) + t] = o4;
}

// ---------------- per-batch column sums of xn ----------------
__global__ void colsum_kernel(const float* __restrict__ xn, float* __restrict__ cs)
{
    int b = blockIdx.y;
    int d = blockIdx.x * 128 + threadIdx.x;
    const float* p = xn + (size_t)b*SS*DD + d;
    float s = 0.f;
    for (int k = 0; k < SS; k++) s += p[(size_t)k*DD];
    cs[b*DD + d] = s;
}

// ---------------- sparsity = (||row||^2 - dot(row, colsum)/S) / sqrt(D) ----
__global__ __launch_bounds__(128) void sparsity_kernel(const float* __restrict__ xn,
        const float* __restrict__ cs, float* __restrict__ sp)
{
    int row = blockIdx.x;
    int b = row >> 11;   // /S
    int t = threadIdx.x;
    float4 v = ((const float4*)xn)[(size_t)row*(DD/4) + t];
    float4 c = ((const float4*)cs)[b*(DD/4) + t];
    double diag = (double)v.x*v.x + (double)v.y*v.y + (double)v.z*v.z + (double)v.w*v.w;
    double dm   = (double)v.x*c.x + (double)v.y*c.y + (double)v.z*c.z + (double)v.w*c.w;
    #pragma unroll
    for (int o = 16; o > 0; o >>= 1) {
        diag += __shfl_down_sync(0xffffffffu, diag, o);
        dm   += __shfl_down_sync(0xffffffffu, dm,   o);
    }
    __shared__ double rd[4], rm[4];
    if ((t & 31) == 0) { rd[t >> 5] = diag; rm[t >> 5] = dm; }
    __syncthreads();
    if (t == 0) {
        double dg = rd[0] + rd[1] + rd[2] + rd[3];
        double mm = rm[0] + rm[1] + rm[2] + rm[3];
        sp[row] = (float)((dg - mm * (1.0/SS)) * 0.04419417382415922);  // 1/sqrt(512)
    }
}

// ---------------- top-39 per batch (iterative argmax in smem) ----------------
__global__ __launch_bounds__(256) void topk_kernel(const float* __restrict__ sp,
        int* __restrict__ tidx)
{
    int b = blockIdx.x;
    int t = threadIdx.x;
    __shared__ float sv[SS];
    __shared__ float rbv[8];
    __shared__ int   rbi[8];
    for (int i = t; i < SS; i += 256) sv[i] = sp[b*SS + i];
    __syncthreads();
    for (int sel = 0; sel < TOPQ; ++sel) {
        float bv = -3.0e38f; int bi = 0;
        for (int i = t; i < SS; i += 256) {
            float v = sv[i];
            if (v > bv || (v == bv && i < bi)) { bv = v; bi = i; }
        }
        #pragma unroll
        for (int o = 16; o > 0; o >>= 1) {
            float ov = __shfl_down_sync(0xffffffffu, bv, o);
            int   oi = __shfl_down_sync(0xffffffffu, bi, o);
            if (ov > bv || (ov == bv && oi < bi)) { bv = ov; bi = oi; }
        }
        if ((t & 31) == 0) { rbv[t >> 5] = bv; rbi[t >> 5] = bi; }
        __syncthreads();
        if (t == 0) {
            float fv = rbv[0]; int fi = rbi[0];
            #pragma unroll
            for (int w = 1; w < 8; w++)
                if (rbv[w] > fv || (rbv[w] == fv && rbi[w] < fi)) { fv = rbv[w]; fi = rbi[w]; }
            tidx[b*TOPQ + sel] = fi;
            sv[fi] = -3.4e38f;
        }
        __syncthreads();
    }
}

// ---------------- small row projection: out[r,:] = row(r) @ W^T + bias -------
// gidx != null: row(r) = src[ (r/TOPQ)*S + gidx[r] ]  (gather);  else src[r]
__global__ __launch_bounds__(256) void rowproj_kernel(const float* __restrict__ src,
        const int* __restrict__ gidx, const float* __restrict__ W,
        const float* __restrict__ bias, float* __restrict__ out)
{
    int r = blockIdx.x;
    __shared__ float xr[DD];
    const float* srow;
    if (gidx) { int b = r / TOPQ; srow = src + ((size_t)b*SS + gidx[r]) * DD; }
    else        srow = src + (size_t)r * DD;
    for (int i = threadIdx.x; i < DD/4; i += 256)
        ((float4*)xr)[i] = ((const float4*)srow)[i];
    __syncthreads();
    for (int j = threadIdx.x; j < DD; j += 256) {
        const float4* w4 = (const float4*)(W + (size_t)j*DD);
        float acc = 0.f;
        #pragma unroll 4
        for (int k = 0; k < DD/4; k++) {
            float4 w = w4[k]; float4 xv = ((float4*)xr)[k];
            acc = fmaf(w.x, xv.x, fmaf(w.y, xv.y, fmaf(w.z, xv.z, fmaf(w.w, xv.w, acc))));
        }
        out[(size_t)r*DD + j] = acc + bias[j];
    }
}

// ---------------- sparse attention: one block per (q-row, head, batch) -------
__global__ __launch_bounds__(256) void attn_kernel(const float* __restrict__ qs,
        const float* __restrict__ kv, float* __restrict__ ctx)
{
    int qi = blockIdx.x, h = blockIdx.y, b = blockIdx.z;
    int t = threadIdx.x;
    __shared__ float q[DH];
    __shared__ float sc[SS];
    __shared__ float red[8];
    __shared__ float cred[4][DH];
    if (t < DH) q[t] = qs[(size_t)(b*TOPQ + qi)*DD + h*DH + t];
    __syncthreads();
    const float4* q4 = (const float4*)q;
    for (int k = t; k < SS; k += 256) {
        const float4* kr = (const float4*)(kv + ((size_t)(b*SS + k))*(2*DD) + h*DH);
        float a = 0.f;
        #pragma unroll
        for (int i = 0; i < DH/4; i++) {
            float4 kk = kr[i]; float4 qq = q4[i];
            a = fmaf(kk.x, qq.x, fmaf(kk.y, qq.y, fmaf(kk.z, qq.z, fmaf(kk.w, qq.w, a))));
        }
        sc[k] = a * 0.125f;   // 1/sqrt(64)
    }
    __syncthreads();
    float m = -1e30f;
    for (int k = t; k < SS; k += 256) m = fmaxf(m, sc[k]);
    #pragma unroll
    for (int o = 16; o > 0; o >>= 1) m = fmaxf(m, __shfl_down_sync(0xffffffffu, m, o));
    if ((t & 31) == 0) red[t >> 5] = m;
    __syncthreads();
    m = red[0];
    #pragma unroll
    for (int w = 1; w < 8; w++) m = fmaxf(m, red[w]);
    __syncthreads();
    float sum = 0.f;
    for (int k = t; k < SS; k += 256) { float p = __expf(sc[k] - m); sc[k] = p; sum += p; }
    #pragma unroll
    for (int o = 16; o > 0; o >>= 1) sum += __shfl_down_sync(0xffffffffu, sum, o);
    if ((t & 31) == 0) red[t >> 5] = sum;
    __syncthreads();
    float tot = red[0]+red[1]+red[2]+red[3]+red[4]+red[5]+red[6]+red[7];
    float inv = 1.0f / tot;
    int d = t & (DH-1);
    int part = t >> 6;
    const float* vb = kv + ((size_t)(b*SS))*(2*DD) + DD + h*DH + d;
    float acc = 0.f;
    int k0 = part * (SS/4), k1 = k0 + SS/4;
    for (int k = k0; k < k1; k++) acc = fmaf(sc[k], vb[(size_t)k*(2*DD)], acc);
    cred[part][d] = acc;
    __syncthreads();
    if (part == 0)
        ctx[(size_t)(b*TOPQ + qi)*DD + h*DH + d] =
            (cred[0][d] + cred[1][d] + cred[2][d] + cred[3][d]) * inv;
}

// ---------------- x2 = x + base (base = colsum/S broadcast) ----------------
__global__ void addbase_kernel(const float* __restrict__ x,
        const float* __restrict__ cs, float* __restrict__ x2)
{
    size_t i = (size_t)blockIdx.x * blockDim.x + threadIdx.x;   // float4 index
    int col4 = (int)(i & 127);
    int row  = (int)(i >> 7);
    int b    = row >> 11;
    float4 xv = ((const float4*)x)[i];
    float4 c  = ((const float4*)cs)[b*(DD/4) + col4];
    const float r = 1.0f / SS;
    ((float4*)x2)[i] = make_float4(xv.x + c.x*r, xv.y + c.y*r, xv.z + c.z*r, xv.w + c.w*r);
}

// ---------------- scatter sparse rows: x2[row] = x[row] + aout[r] ------------
__global__ __launch_bounds__(128) void scatter_kernel(const float* __restrict__ x,
        const float* __restrict__ aout, const int* __restrict__ tidx,
        float* __restrict__ x2)
{
    int r = blockIdx.x;
    int b = r / TOPQ;
    int srow = b*SS + tidx[r];
    int t = threadIdx.x;
    float4 xv = ((const float4*)x)[(size_t)srow*(DD/4) + t];
    float4 a  = ((const float4*)aout)[(size_t)r*(DD/4) + t];
    ((float4*)x2)[(size_t)srow*(DD/4) + t] =
        make_float4(xv.x + a.x, xv.y + a.y, xv.z + a.z, xv.w + a.w);
}

// ---------------- fp32 GEMM: C[M,N] = A[M,K] @ W[N,K]^T + bias (+epi) --------
__device__ __forceinline__ float gelu_f(float x) {
    return 0.5f * x * (1.0f + erff(x * 0.7071067811865476f));
}

#define GBM 128
#define GBN 128
#define GBK 16

template<int EPI>   // 0 = none, 1 = gelu, 2 = +res
__global__ __launch_bounds__(256) void gemm_kernel(
    const float* __restrict__ A, const float* __restrict__ W,
    const float* __restrict__ bias, const float* __restrict__ res,
    float* __restrict__ C, int M, int N, int K)
{
    __shared__ float As[GBK][GBM+4];
    __shared__ float Bs[GBK][GBN+4];
    const int bm = blockIdx.y * GBM;
    const int bn = blockIdx.x * GBN;
    const int tid = threadIdx.x;
    const int tx = tid & 15;
    const int ty = tid >> 4;

    float acc[8][8];
    #pragma unroll
    for (int i = 0; i < 8; i++)
        #pragma unroll
        for (int j = 0; j < 8; j++) acc[i][j] = 0.f;

    const float* Ag = A + (size_t)bm * K;
    const float* Wg = W + (size_t)bn * K;

    float4 pa[2], pb[2];
    #pragma unroll
    for (int i = 0; i < 2; i++) {
        int f = tid + i*256;
        pa[i] = *(const float4*)(Ag + (size_t)(f >> 2)*K + ((f & 3) << 2));
        pb[i] = *(const float4*)(Wg + (size_t)(f >> 2)*K + ((f & 3) << 2));
    }
    const int nk = K / GBK;
    for (int kt = 0; kt < nk; ++kt) {
        #pragma unroll
        for (int i = 0; i < 2; i++) {
            int f = tid + i*256;
            int r = f >> 2, c = (f & 3) << 2;
            As[c+0][r] = pa[i].x; As[c+1][r] = pa[i].y; As[c+2][r] = pa[i].z; As[c+3][r] = pa[i].w;
            Bs[c+0][r] = pb[i].x; Bs[c+1][r] = pb[i].y; Bs[c+2][r] = pb[i].z; Bs[c+3][r] = pb[i].w;
        }
        __syncthreads();
        if (kt + 1 < nk) {
            int ko = (kt + 1) * GBK;
            #pragma unroll
            for (int i = 0; i < 2; i++) {
                int f = tid + i*256;
                pa[i] = *(const float4*)(Ag + (size_t)(f >> 2)*K + ko + ((f & 3) << 2));
                pb[i] = *(const float4*)(Wg + (size_t)(f >> 2)*K + ko + ((f & 3) << 2));
            }
        }
        #pragma unroll
        for (int k = 0; k < GBK; k++) {
            float4 a0 = *(const float4*)&As[k][ty*8];
            float4 a1 = *(const float4*)&As[k][ty*8 + 4];
            float4 b0 = *(const float4*)&Bs[k][tx*8];
            float4 b1 = *(const float4*)&Bs[k][tx*8 + 4];
            float ar[8] = {a0.x,a0.y,a0.z,a0.w,a1.x,a1.y,a1.z,a1.w};
            float br[8] = {b0.x,b0.y,b0.z,b0.w,b1.x,b1.y,b1.z,b1.w};
            #pragma unroll
            for (int i = 0; i < 8; i++)
                #pragma unroll
                for (int j = 0; j < 8; j++)
                    acc[i][j] = fmaf(ar[i], br[j], acc[i][j]);
        }
        __syncthreads();
    }
    const int row0 = bm + ty*8;
    const int col0 = bn + tx*8;
    #pragma unroll
    for (int i = 0; i < 8; i++) {
        int row = row0 + i;
        #pragma unroll
        for (int j = 0; j < 8; j++) {
            float v = acc[i][j] + bias[col0 + j];
            if (EPI == 1) v = gelu_f(v);
            if (EPI == 2) v += res[(size_t)row*N + col0 + j];
            C[(size_t)row*N + col0 + j] = v;
        }
    }
}

// ---------------- ratio tail ----------------
__global__ void ratio_kernel(float* out, int out_size)
{
    int i = NROWS*DD + blockIdx.x*blockDim.x + threadIdx.x;
    if (i < out_size) out[i] = (float)TOPQ / (float)SS;   // 39/2048
}

// ---------------- launch ----------------
extern "C" void kernel_launch(void* const* d_in, const int* in_sizes, int n_in,
                              void* d_out, int out_size)
{
    const float* x    = (const float*)d_in[0];
    const float* ln1g = (const float*)d_in[1];
    const float* ln1b = (const float*)d_in[2];
    const float* in_w = (const float*)d_in[3];
    const float* in_b = (const float*)d_in[4];
    const float* outw = (const float*)d_in[5];
    const float* outb = (const float*)d_in[6];
    const float* ln2g = (const float*)d_in[7];
    const float* ln2b = (const float*)d_in[8];
    const float* w1   = (const float*)d_in[9];
    const float* b1   = (const float*)d_in[10];
    const float* w2   = (const float*)d_in[11];
    const float* b2   = (const float*)d_in[12];
    float* out = (float*)d_out;

    float *xn, *x2, *xn2, *kv, *h1, *cs, *sp, *qs, *ctx, *aout;
    int *tidx;
    cudaGetSymbolAddress((void**)&xn,   g_xn);
    cudaGetSymbolAddress((void**)&x2,   g_x2);
    cudaGetSymbolAddress((void**)&xn2,  g_xn2);
    cudaGetSymbolAddress((void**)&kv,   g_kv);
    cudaGetSymbolAddress((void**)&h1,   g_h1);
    cudaGetSymbolAddress((void**)&cs,   g_cs);
    cudaGetSymbolAddress((void**)&sp,   g_sp);
    cudaGetSymbolAddress((void**)&qs,   g_qs);
    cudaGetSymbolAddress((void**)&ctx,  g_ctx);
    cudaGetSymbolAddress((void**)&aout, g_aout);
    cudaGetSymbolAddress((void**)&tidx, g_tidx);

    // 1) layernorm1
    ln_kernel<<<NROWS, 128>>>(x, ln1g, ln1b, xn);
    // 2) column sums (also provides base = cs/S)
    colsum_kernel<<<dim3(DD/128, BB), 128>>>(xn, cs);
    // 3) sparsity measure (analytic: max = diagonal, mean is linear)
    sparsity_kernel<<<NROWS, 128>>>(xn, cs, sp);
    // 4) top-39 per batch
    topk_kernel<<<BB, 256>>>(sp, tidx);
    // 5) gather + Q projection (W_q = in_w rows [0, D))
    rowproj_kernel<<<BB*TOPQ, 256>>>(xn, tidx, in_w, in_b, qs);
    // 6) fused K+V projection (in_w rows [D, 3D))
    gemm_kernel<0><<<dim3((2*DD)/GBN, NROWS/GBM), 256>>>(
        xn, in_w + (size_t)DD*DD, in_b + DD, nullptr, kv, NROWS, 2*DD, DD);
    // 7) attention over sparse queries
    attn_kernel<<<dim3(TOPQ, HH, BB), 256>>>(qs, kv, ctx);
    // 8) output projection
    rowproj_kernel<<<BB*TOPQ, 256>>>(ctx, nullptr, outw, outb, aout);
    // 9) x2 = x + base  then overwrite sparse rows with x + ctx_out
    addbase_kernel<<<(NROWS*(DD/4))/256, 256>>>(x, cs, x2);
    scatter_kernel<<<BB*TOPQ, 128>>>(x, aout, tidx, x2);
    // 10) layernorm2
    ln_kernel<<<NROWS, 128>>>(x2, ln2g, ln2b, xn2);
    // 11) FFN
    gemm_kernel<1><<<dim3(FF_/GBN, NROWS/GBM), 256>>>(
        xn2, w1, b1, nullptr, h1, NROWS, FF_, DD);
    gemm_kernel<2><<<dim3(DD/GBN, NROWS/GBM), 256>>>(
        h1, w2, b2, x2, out, NROWS, DD, FF_);
    // 12) ratio tail (tuple second element), if present in out buffer
    if (out_size > NROWS*DD) {
        int tail = out_size - NROWS*DD;
        ratio_kernel<<<(tail + 255)/256, 256>>>(out, out_size);
    }
}

// round 3
// speedup vs baseline: 2.0528x; 2.0528x over previous
#include <cuda_runtime.h>
#include <math.h>
#include <stdint.h>

#define BB 8
#define SS 2048
#define DD 512
#define FF_ 2048
#define HH 8
#define DH 64
#define TOPQ 39
#define NROWS (BB*SS)   /* 16384 */

// ---------------- static scratch ----------------
__device__ float g_xn  [NROWS*DD];
__device__ float g_x2  [NROWS*DD];
__device__ float g_xn2 [NROWS*DD];
__device__ float g_kv  [NROWS*2*DD];
__device__ float g_h1  [(size_t)NROWS*FF_];
__device__ float g_cs  [BB*DD];
__device__ float g_cspart[16*BB*DD];
__device__ float g_sp  [BB*SS];
__device__ int   g_tidx[BB*TOPQ];
__device__ float g_qs  [BB*TOPQ*DD];
__device__ float g_ctx [BB*TOPQ*DD];
__device__ float g_ctxp[4*BB*TOPQ*DD];
__device__ float g_aout[BB*TOPQ*DD];
__device__ float g_scores[(size_t)BB*HH*TOPQ*SS];

// ---------------- helpers ----------------
__device__ __forceinline__ float tf32r(float x) {
    float r; asm("cvt.rna.tf32.f32 %0, %1;" : "=f"(r) : "f"(x)); return r;
}
__device__ __forceinline__ void mma_tf32(float* d, const float4& a, const float2& b) {
    const uint32_t* A = reinterpret_cast<const uint32_t*>(&a);
    const uint32_t* B = reinterpret_cast<const uint32_t*>(&b);
    asm volatile("mma.sync.aligned.m16n8k8.row.col.f32.tf32.tf32.f32 "
        "{%0,%1,%2,%3}, {%4,%5,%6,%7}, {%8,%9}, {%0,%1,%2,%3};"
        : "+f"(d[0]), "+f"(d[1]), "+f"(d[2]), "+f"(d[3])
        : "r"(A[0]), "r"(A[1]), "r"(A[2]), "r"(A[3]), "r"(B[0]), "r"(B[1]));
}
__device__ __forceinline__ float gelu_f(float x) {
    return 0.5f * x * (1.0f + erff(x * 0.7071067811865476f));
}

// ====================================================================
// tf32 tensor-core GEMM via mma.sync: C[M,N] = A[M,K] @ W[N,K]^T + bias (+epi)
// CTA 128x128, K-chunk 32, 256 threads = 8 warps (2M x 4N), warp tile 64x32.
// SMEM holds tiles in mma-fragment order; double buffered.
// Buffer layout (floats): buf*8192 + [A: ((s*8+mb)*32+slot)*4 + aidx]
//                                    [B: 4096 + ((s*16+nb)*32+slot)*2 + bidx]
// slot = lane ^ s  (XOR swizzle for conflict-free access)
// ====================================================================
#define GSMEM (2*8192*4)

template<int EPI>   // 0=none, 1=gelu, 2=+res
__global__ __launch_bounds__(256) void tc_gemm(
    const float* __restrict__ A, const float* __restrict__ W,
    const float* __restrict__ bias, const float* __restrict__ res,
    float* __restrict__ C, int N, int K)
{
    extern __shared__ float sm[];
    const int tid  = threadIdx.x;
    const int lane = tid & 31;
    const int wid  = tid >> 5;
    const int wm   = wid >> 2;      // 0..1  (M)
    const int wn   = wid & 3;       // 0..3  (N)
    const int bm = blockIdx.y * 128;
    const int bn = blockIdx.x * 128;

    const float* Ab = A + (size_t)bm * K;
    const float* Wb = W + (size_t)bn * K;

    float4 ar[4], br[4];

    auto LOAD = [&](int kbase) {
        #pragma unroll
        for (int i = 0; i < 4; i++) {
            int idx = i*256 + tid;
            int row = idx >> 3, seg = idx & 7;
            ar[i] = *(const float4*)(Ab + (size_t)row*K + kbase + seg*4);
            br[i] = *(const float4*)(Wb + (size_t)row*K + kbase + seg*4);
        }
    };
    auto STORE = [&](int buf) {
        float* base = sm + buf*8192;
        #pragma unroll
        for (int i = 0; i < 4; i++) {
            int idx = i*256 + tid;
            int row = idx >> 3, seg = idx & 7;
            int s   = seg >> 1;               // k8 step
            int mb  = row >> 4;               // A m16 tile
            int nb  = row >> 3;               // B n8 tile
            int aidx = ((row >> 3) & 1) + 2*(seg & 1);
            int bidx = seg & 1;
            float av[4] = {ar[i].x, ar[i].y, ar[i].z, ar[i].w};
            float bv[4] = {br[i].x, br[i].y, br[i].z, br[i].w};
            #pragma unroll
            for (int j = 0; j < 4; j++) {
                int slot = (((row & 7) << 2) + j) ^ s;
                base[((s*8 + mb)*32 + slot)*4 + aidx]         = tf32r(av[j]);
                base[4096 + ((s*16 + nb)*32 + slot)*2 + bidx] = tf32r(bv[j]);
            }
        }
    };

    float acc[4][4][4];
    #pragma unroll
    for (int a = 0; a < 4; a++)
        #pragma unroll
        for (int b = 0; b < 4; b++)
            #pragma unroll
            for (int c = 0; c < 4; c++) acc[a][b][c] = 0.f;

    const int nk = K >> 5;
    LOAD(0);
    STORE(0);
    __syncthreads();

    for (int kt = 0; kt < nk; kt++) {
        int buf = kt & 1;
        if (kt + 1 < nk) LOAD((kt + 1) << 5);
        const float* base = sm + buf*8192;
        #pragma unroll
        for (int s = 0; s < 4; s++) {
            int slot = lane ^ s;
            float4 af[4];
            float2 bf[4];
            #pragma unroll
            for (int mt = 0; mt < 4; mt++)
                af[mt] = *(const float4*)&base[((s*8 + wm*4 + mt)*32 + slot)*4];
            #pragma unroll
            for (int nt = 0; nt < 4; nt++)
                bf[nt] = *(const float2*)&base[4096 + ((s*16 + wn*4 + nt)*32 + slot)*2];
            #pragma unroll
            for (int mt = 0; mt < 4; mt++)
                #pragma unroll
                for (int nt = 0; nt < 4; nt++)
                    mma_tf32(acc[mt][nt], af[mt], bf[nt]);
        }
        if (kt + 1 < nk) {
            STORE(buf ^ 1);
            __syncthreads();
        }
    }

    // epilogue: c0,c1 -> (row, col..col+1); c2,c3 -> (row+8, ...)
    const int g = lane >> 2, t = lane & 3;
    #pragma unroll
    for (int mt = 0; mt < 4; mt++) {
        int row0 = bm + wm*64 + mt*16 + g;
        #pragma unroll
        for (int nt = 0; nt < 4; nt++) {
            int col = bn + wn*32 + nt*8 + 2*t;
            float b0 = bias[col], b1 = bias[col+1];
            float v0 = acc[mt][nt][0] + b0;
            float v1 = acc[mt][nt][1] + b1;
            float v2 = acc[mt][nt][2] + b0;
            float v3 = acc[mt][nt][3] + b1;
            if (EPI == 1) {
                v0 = gelu_f(v0); v1 = gelu_f(v1); v2 = gelu_f(v2); v3 = gelu_f(v3);
            }
            if (EPI == 2) {
                const float* r0 = res + (size_t)row0*N + col;
                const float* r1 = res + (size_t)(row0+8)*N + col;
                v0 += r0[0]; v1 += r0[1]; v2 += r1[0]; v3 += r1[1];
            }
            *(float2*)&C[(size_t)row0*N + col]     = make_float2(v0, v1);
            *(float2*)&C[(size_t)(row0+8)*N + col] = make_float2(v2, v3);
        }
    }
}

// ---------------- layernorm ----------------
__global__ __launch_bounds__(128) void ln_kernel(const float* __restrict__ x,
        const float* __restrict__ g, const float* __restrict__ bb,
        float* __restrict__ out)
{
    int row = blockIdx.x;
    int t   = threadIdx.x;
    float4 v = ((const float4*)x)[(size_t)row*(DD/4) + t];
    float s = v.x + v.y + v.z + v.w;
    __shared__ float red[4];
    #pragma unroll
    for (int o = 16; o > 0; o >>= 1) s += __shfl_down_sync(0xffffffffu, s, o);
    if ((t & 31) == 0) red[t >> 5] = s;
    __syncthreads();
    float mean = (red[0] + red[1] + red[2] + red[3]) * (1.0f/DD);
    __syncthreads();
    float dx = v.x - mean, dy = v.y - mean, dz = v.z - mean, dw = v.w - mean;
    float q = dx*dx + dy*dy + dz*dz + dw*dw;
    #pragma unroll
    for (int o = 16; o > 0; o >>= 1) q += __shfl_down_sync(0xffffffffu, q, o);
    if ((t & 31) == 0) red[t >> 5] = q;
    __syncthreads();
    float var = (red[0] + red[1] + red[2] + red[3]) * (1.0f/DD);
    float inv = rsqrtf(var + 1e-5f);
    float4 gg = ((const float4*)g)[t];
    float4 bv = ((const float4*)bb)[t];
    ((float4*)out)[(size_t)row*(DD/4) + t] =
        make_float4(dx*inv*gg.x + bv.x, dy*inv*gg.y + bv.y,
                    dz*inv*gg.z + bv.z, dw*inv*gg.w + bv.w);
}

// ---------------- column sums, two-stage deterministic ----------------
__global__ void colsum1_kernel(const float* __restrict__ xn, float* __restrict__ part)
{
    int b = blockIdx.y;
    int c = blockIdx.z;
    int d = blockIdx.x * 128 + threadIdx.x;
    const float* p = xn + (size_t)b*SS*DD + (size_t)c*128*DD + d;
    float s = 0.f;
    #pragma unroll 8
    for (int k = 0; k < 128; k++) s += p[(size_t)k*DD];
    part[((size_t)c*BB + b)*DD + d] = s;
}
__global__ void colsum2_kernel(const float* __restrict__ part, float* __restrict__ cs)
{
    int i = blockIdx.x * 256 + threadIdx.x;
    if (i < BB*DD) {
        float s = 0.f;
        #pragma unroll
        for (int c = 0; c < 16; c++) s += part[(size_t)c*BB*DD + i];
        cs[i] = s;
    }
}

// ---------------- sparsity = (||row||^2 - dot(row, colsum)/S) / sqrt(D) ----
__global__ __launch_bounds__(128) void sparsity_kernel(const float* __restrict__ xn,
        const float* __restrict__ cs, float* __restrict__ sp)
{
    int row = blockIdx.x;
    int b = row >> 11;
    int t = threadIdx.x;
    float4 v = ((const float4*)xn)[(size_t)row*(DD/4) + t];
    float4 c = ((const float4*)cs)[b*(DD/4) + t];
    double diag = (double)v.x*v.x + (double)v.y*v.y + (double)v.z*v.z + (double)v.w*v.w;
    double dm   = (double)v.x*c.x + (double)v.y*c.y + (double)v.z*c.z + (double)v.w*c.w;
    #pragma unroll
    for (int o = 16; o > 0; o >>= 1) {
        diag += __shfl_down_sync(0xffffffffu, diag, o);
        dm   += __shfl_down_sync(0xffffffffu, dm,   o);
    }
    __shared__ double rd[4], rm[4];
    if ((t & 31) == 0) { rd[t >> 5] = diag; rm[t >> 5] = dm; }
    __syncthreads();
    if (t == 0) {
        double dg = rd[0] + rd[1] + rd[2] + rd[3];
        double mm = rm[0] + rm[1] + rm[2] + rm[3];
        sp[row] = (float)((dg - mm * (1.0/SS)) * 0.04419417382415922);
    }
}

// ---------------- top-39 ----------------
__global__ __launch_bounds__(256) void topk_kernel(const float* __restrict__ sp,
        int* __restrict__ tidx)
{
    int b = blockIdx.x;
    int t = threadIdx.x;
    __shared__ float sv[SS];
    __shared__ float rbv[8];
    __shared__ int   rbi[8];
    for (int i = t; i < SS; i += 256) sv[i] = sp[b*SS + i];
    __syncthreads();
    for (int sel = 0; sel < TOPQ; ++sel) {
        float bv = -3.0e38f; int bi = 0;
        for (int i = t; i < SS; i += 256) {
            float v = sv[i];
            if (v > bv || (v == bv && i < bi)) { bv = v; bi = i; }
        }
        #pragma unroll
        for (int o = 16; o > 0; o >>= 1) {
            float ov = __shfl_down_sync(0xffffffffu, bv, o);
            int   oi = __shfl_down_sync(0xffffffffu, bi, o);
            if (ov > bv || (ov == bv && oi < bi)) { bv = ov; bi = oi; }
        }
        if ((t & 31) == 0) { rbv[t >> 5] = bv; rbi[t >> 5] = bi; }
        __syncthreads();
        if (t == 0) {
            float fv = rbv[0]; int fi = rbi[0];
            #pragma unroll
            for (int w = 1; w < 8; w++)
                if (rbv[w] > fv || (rbv[w] == fv && rbi[w] < fi)) { fv = rbv[w]; fi = rbi[w]; }
            tidx[b*TOPQ + sel] = fi;
            sv[fi] = -3.4e38f;
        }
        __syncthreads();
    }
}

// ---------------- small row projection ----------------
__global__ __launch_bounds__(256) void rowproj_kernel(const float* __restrict__ src,
        const int* __restrict__ gidx, const float* __restrict__ W,
        const float* __restrict__ bias, float* __restrict__ out)
{
    int r = blockIdx.x;
    __shared__ float xr[DD];
    const float* srow;
    if (gidx) { int b = r / TOPQ; srow = src + ((size_t)b*SS + gidx[r]) * DD; }
    else        srow = src + (size_t)r * DD;
    for (int i = threadIdx.x; i < DD/4; i += 256)
        ((float4*)xr)[i] = ((const float4*)srow)[i];
    __syncthreads();
    for (int j = threadIdx.x; j < DD; j += 256) {
        const float4* w4 = (const float4*)(W + (size_t)j*DD);
        float acc = 0.f;
        #pragma unroll 4
        for (int k = 0; k < DD/4; k++) {
            float4 w = w4[k]; float4 xv = ((float4*)xr)[k];
            acc = fmaf(w.x, xv.x, fmaf(w.y, xv.y, fmaf(w.z, xv.z, fmaf(w.w, xv.w, acc))));
        }
        out[(size_t)r*DD + j] = acc + bias[j];
    }
}

// ---------------- attention: scores (K-tiled, shared across queries) --------
__global__ __launch_bounds__(256) void scorek_kernel(const float* __restrict__ qs,
        const float* __restrict__ kv, float* __restrict__ sc)
{
    int kt = blockIdx.x, h = blockIdx.y, b = blockIdx.z;
    __shared__ float Qt[DH][TOPQ+1];
    __shared__ float Ks[128][DH];
    int tid = threadIdx.x;
    for (int i = tid; i < TOPQ*DH; i += 256) {
        int q = i % TOPQ, d = i / TOPQ;
        Qt[d][q] = qs[((size_t)(b*TOPQ+q))*DD + h*DH + d];
    }
    for (int i = tid; i < 128*16; i += 256) {
        int row = i >> 4, c4 = i & 15;
        *(float4*)&Ks[row][c4*4] =
            *(const float4*)(kv + ((size_t)(b*SS + kt*128 + row))*(2*DD) + h*DH + c4*4);
    }
    __syncthreads();
    for (int p = tid; p < TOPQ*128; p += 256) {
        int q = p % TOPQ, k = p / TOPQ;
        float a = 0.f;
        #pragma unroll 8
        for (int d = 0; d < DH; d++) a = fmaf(Qt[d][q], Ks[k][d], a);
        sc[((size_t)(b*HH+h)*TOPQ + q)*SS + kt*128 + k] = a * 0.125f;
    }
}

// ---------------- attention: row softmax (in place, normalized) --------------
__global__ __launch_bounds__(256) void softmax_kernel(float* __restrict__ sc)
{
    size_t base = (size_t)blockIdx.x * SS;
    int t = threadIdx.x;
    float4* p = (float4*)(sc + base);
    float4 v0 = p[t], v1 = p[t + 256];
    __shared__ float red[8];
    float m = fmaxf(fmaxf(fmaxf(v0.x, v0.y), fmaxf(v0.z, v0.w)),
                    fmaxf(fmaxf(v1.x, v1.y), fmaxf(v1.z, v1.w)));
    #pragma unroll
    for (int o = 16; o > 0; o >>= 1) m = fmaxf(m, __shfl_down_sync(0xffffffffu, m, o));
    if ((t & 31) == 0) red[t >> 5] = m;
    __syncthreads();
    m = red[0];
    #pragma unroll
    for (int w = 1; w < 8; w++) m = fmaxf(m, red[w]);
    __syncthreads();
    v0.x = __expf(v0.x - m); v0.y = __expf(v0.y - m);
    v0.z = __expf(v0.z - m); v0.w = __expf(v0.w - m);
    v1.x = __expf(v1.x - m); v1.y = __expf(v1.y - m);
    v1.z = __expf(v1.z - m); v1.w = __expf(v1.w - m);
    float s = v0.x+v0.y+v0.z+v0.w + v1.x+v1.y+v1.z+v1.w;
    #pragma unroll
    for (int o = 16; o > 0; o >>= 1) s += __shfl_down_sync(0xffffffffu, s, o);
    if ((t & 31) == 0) red[t >> 5] = s;
    __syncthreads();
    float tot = red[0]+red[1]+red[2]+red[3]+red[4]+red[5]+red[6]+red[7];
    float inv = 1.0f / tot;
    v0.x*=inv; v0.y*=inv; v0.z*=inv; v0.w*=inv;
    v1.x*=inv; v1.y*=inv; v1.z*=inv; v1.w*=inv;
    p[t] = v0; p[t + 256] = v1;
}

// ---------------- attention: probs @ V (k-split partials) --------------------
__global__ __launch_bounds__(256) void ctxv_kernel(const float* __restrict__ pr_g,
        const float* __restrict__ kv, float* __restrict__ part)
{
    int g = blockIdx.x, h = blockIdx.y, b = blockIdx.z;
    __shared__ float Vt[64][64];
    __shared__ float Pt[TOPQ][64];
    int tid = threadIdx.x, w = tid >> 5, lid = tid & 31;
    float acc[5][2];
    #pragma unroll
    for (int i = 0; i < 5; i++) { acc[i][0] = 0.f; acc[i][1] = 0.f; }
    for (int t = 0; t < 8; t++) {
        int k0 = g * 512 + t * 64;
        for (int i = tid; i < 64*16; i += 256) {
            int row = i >> 4, c4 = i & 15;
            *(float4*)&Vt[row][c4*4] =
                *(const float4*)(kv + ((size_t)(b*SS + k0 + row))*(2*DD) + DD + h*DH + c4*4);
        }
        for (int i = tid; i < TOPQ*64; i += 256) {
            int q = i >> 6, kk = i & 63;
            Pt[q][kk] = pr_g[((size_t)(b*HH+h)*TOPQ + q)*SS + k0 + kk];
        }
        __syncthreads();
        int ii = 0;
        for (int q = w; q < TOPQ; q += 8, ii++) {
            float a0 = acc[ii][0], a1 = acc[ii][1];
            #pragma unroll 8
            for (int kk = 0; kk < 64; kk++) {
                float2 v = *(float2*)&Vt[kk][2*lid];
                float pp = Pt[q][kk];
                a0 = fmaf(pp, v.x, a0); a1 = fmaf(pp, v.y, a1);
            }
            acc[ii][0] = a0; acc[ii][1] = a1;
        }
        __syncthreads();
    }
    int ii = 0;
    for (int q = w; q < TOPQ; q += 8, ii++) {
        float* dst = part + (size_t)g*(BB*TOPQ*DD) + ((size_t)(b*TOPQ+q))*DD + h*DH + 2*lid;
        *(float2*)dst = make_float2(acc[ii][0], acc[ii][1]);
    }
}
__global__ void ctxred_kernel(const float* __restrict__ p, float* __restrict__ ctx)
{
    const int N1 = BB*TOPQ*DD;
    int i = blockIdx.x * 256 + threadIdx.x;
    if (i < N1) ctx[i] = p[i] + p[i+N1] + p[i+2*N1] + p[i+3*N1];
}

// ---------------- x2 = x + base ----------------
__global__ void addbase_kernel(const float* __restrict__ x,
        const float* __restrict__ cs, float* __restrict__ x2)
{
    size_t i = (size_t)blockIdx.x * blockDim.x + threadIdx.x;
    int col4 = (int)(i & 127);
    int row  = (int)(i >> 7);
    int b    = row >> 11;
    float4 xv = ((const float4*)x)[i];
    float4 c  = ((const float4*)cs)[b*(DD/4) + col4];
    const float r = 1.0f / SS;
    ((float4*)x2)[i] = make_float4(xv.x + c.x*r, xv.y + c.y*r, xv.z + c.z*r, xv.w + c.w*r);
}

// ---------------- scatter sparse rows ----------------
__global__ __launch_bounds__(128) void scatter_kernel(const float* __restrict__ x,
        const float* __restrict__ aout, const int* __restrict__ tidx,
        float* __restrict__ x2)
{
    int r = blockIdx.x;
    int b = r / TOPQ;
    int srow = b*SS + tidx[r];
    int t = threadIdx.x;
    float4 xv = ((const float4*)x)[(size_t)srow*(DD/4) + t];
    float4 a  = ((const float4*)aout)[(size_t)r*(DD/4) + t];
    ((float4*)x2)[(size_t)srow*(DD/4) + t] =
        make_float4(xv.x + a.x, xv.y + a.y, xv.z + a.z, xv.w + a.w);
}

// ---------------- ratio tail ----------------
__global__ void ratio_kernel(float* out, int out_size)
{
    int i = NROWS*DD + blockIdx.x*blockDim.x + threadIdx.x;
    if (i < out_size) out[i] = (float)TOPQ / (float)SS;
}

// ---------------- launch ----------------
extern "C" void kernel_launch(void* const* d_in, const int* in_sizes, int n_in,
                              void* d_out, int out_size)
{
    const float* x    = (const float*)d_in[0];
    const float* ln1g = (const float*)d_in[1];
    const float* ln1b = (const float*)d_in[2];
    const float* in_w = (const float*)d_in[3];
    const float* in_b = (const float*)d_in[4];
    const float* outw = (const float*)d_in[5];
    const float* outb = (const float*)d_in[6];
    const float* ln2g = (const float*)d_in[7];
    const float* ln2b = (const float*)d_in[8];
    const float* w1   = (const float*)d_in[9];
    const float* b1   = (const float*)d_in[10];
    const float* w2   = (const float*)d_in[11];
    const float* b2   = (const float*)d_in[12];
    float* out = (float*)d_out;

    float *xn, *x2, *xn2, *kv, *h1, *cs, *csp, *sp, *qs, *ctx, *ctxp, *aout, *scores;
    int *tidx;
    cudaGetSymbolAddress((void**)&xn,    g_xn);
    cudaGetSymbolAddress((void**)&x2,    g_x2);
    cudaGetSymbolAddress((void**)&xn2,   g_xn2);
    cudaGetSymbolAddress((void**)&kv,    g_kv);
    cudaGetSymbolAddress((void**)&h1,    g_h1);
    cudaGetSymbolAddress((void**)&cs,    g_cs);
    cudaGetSymbolAddress((void**)&csp,   g_cspart);
    cudaGetSymbolAddress((void**)&sp,    g_sp);
    cudaGetSymbolAddress((void**)&qs,    g_qs);
    cudaGetSymbolAddress((void**)&ctx,   g_ctx);
    cudaGetSymbolAddress((void**)&ctxp,  g_ctxp);
    cudaGetSymbolAddress((void**)&aout,  g_aout);
    cudaGetSymbolAddress((void**)&scores,g_scores);
    cudaGetSymbolAddress((void**)&tidx,  g_tidx);

    cudaFuncSetAttribute(tc_gemm<0>, cudaFuncAttributeMaxDynamicSharedMemorySize, GSMEM);
    cudaFuncSetAttribute(tc_gemm<1>, cudaFuncAttributeMaxDynamicSharedMemorySize, GSMEM);
    cudaFuncSetAttribute(tc_gemm<2>, cudaFuncAttributeMaxDynamicSharedMemorySize, GSMEM);

    // 1) layernorm1
    ln_kernel<<<NROWS, 128>>>(x, ln1g, ln1b, xn);
    // 2) column sums (deterministic two-stage)
    colsum1_kernel<<<dim3(DD/128, BB, 16), 128>>>(xn, csp);
    colsum2_kernel<<<(BB*DD + 255)/256, 256>>>(csp, cs);
    // 3) analytic sparsity (max = diagonal, mean linear)
    sparsity_kernel<<<NROWS, 128>>>(xn, cs, sp);
    // 4) top-39 per batch
    topk_kernel<<<BB, 256>>>(sp, tidx);
    // 5) gather + Q projection
    rowproj_kernel<<<BB*TOPQ, 256>>>(xn, tidx, in_w, in_b, qs);
    // 6) fused K+V projection (tf32 mma.sync)
    tc_gemm<0><<<dim3((2*DD)/128, NROWS/128), 256, GSMEM>>>(
        xn, in_w + (size_t)DD*DD, in_b + DD, nullptr, kv, 2*DD, DD);
    // 7) attention: scores -> softmax -> probs@V
    scorek_kernel<<<dim3(SS/128, HH, BB), 256>>>(qs, kv, scores);
    softmax_kernel<<<BB*HH*TOPQ, 256>>>(scores);
    ctxv_kernel<<<dim3(4, HH, BB), 256>>>(scores, kv, ctxp);
    ctxred_kernel<<<(BB*TOPQ*DD + 255)/256, 256>>>(ctxp, ctx);
    // 8) output projection
    rowproj_kernel<<<BB*TOPQ, 256>>>(ctx, nullptr, outw, outb, aout);
    // 9) residual: base everywhere, sparse rows overwritten
    addbase_kernel<<<(NROWS*(DD/4))/256, 256>>>(x, cs, x2);
    scatter_kernel<<<BB*TOPQ, 128>>>(x, aout, tidx, x2);
    // 10) layernorm2
    ln_kernel<<<NROWS, 128>>>(x2, ln2g, ln2b, xn2);
    // 11) FFN (tf32 mma.sync)
    tc_gemm<1><<<dim3(FF_/128, NROWS/128), 256, GSMEM>>>(
        xn2, w1, b1, nullptr, h1, FF_, DD);
    tc_gemm<2><<<dim3(DD/128, NROWS/128), 256, GSMEM>>>(
        h1, w2, b2, x2, out, DD, FF_);
    // 12) ratio tail
    if (out_size > NROWS*DD) {
        int tail = out_size - NROWS*DD;
        ratio_kernel<<<(tail + 255)/256, 256>>>(out, out_size);
    }
}

// round 4
// speedup vs baseline: 2.4647x; 1.2006x over previous
#include <cuda_runtime.h>
#include <cuda_fp16.h>
#include <math.h>
#include <stdint.h>

#define BB 8
#define SS 2048
#define DD 512
#define FF_ 2048
#define HH 8
#define DH 64
#define TOPQ 39
#define NROWS (BB*SS)   /* 16384 */

// ---------------- static scratch ----------------
__device__ float g_xn  [NROWS*DD];
__device__ float g_x2  [NROWS*DD];
__device__ float g_xn2 [NROWS*DD];
__device__ float g_kv  [NROWS*2*DD];
__device__ float g_h1  [(size_t)NROWS*FF_];
__device__ float g_cs  [BB*DD];
__device__ float g_cspart[16*BB*DD];
__device__ float g_sp  [BB*SS];
__device__ int   g_tidx[BB*TOPQ];
__device__ float g_qs  [BB*TOPQ*DD];
__device__ float g_ctxp[4*BB*TOPQ*DD];
__device__ float g_aout[BB*TOPQ*DD];
__device__ float g_scores[(size_t)BB*HH*TOPQ*SS];

// ---------------- helpers ----------------
__device__ __forceinline__ uint32_t s2u(const void* p) {
    uint32_t a;
    asm("{ .reg .u64 t; cvta.to.shared.u64 t, %1; cvt.u32.u64 %0, t; }" : "=r"(a) : "l"(p));
    return a;
}
__device__ __forceinline__ void mma_f16(float* d, const uint32_t* a, const uint32_t* b) {
    asm volatile("mma.sync.aligned.m16n8k16.row.col.f32.f16.f16.f32 "
        "{%0,%1,%2,%3}, {%4,%5,%6,%7}, {%8,%9}, {%0,%1,%2,%3};"
        : "+f"(d[0]), "+f"(d[1]), "+f"(d[2]), "+f"(d[3])
        : "r"(a[0]), "r"(a[1]), "r"(a[2]), "r"(a[3]), "r"(b[0]), "r"(b[1]));
}
__device__ __forceinline__ void ldsm4(uint32_t* r, uint32_t addr) {
    asm volatile("ldmatrix.sync.aligned.m8n8.x4.shared.b16 {%0,%1,%2,%3}, [%4];"
        : "=r"(r[0]), "=r"(r[1]), "=r"(r[2]), "=r"(r[3]) : "r"(addr));
}
__device__ __forceinline__ float gelu_f(float x) {
    return 0.5f * x * (1.0f + erff(x * 0.7071067811865476f));
}

// ====================================================================
// fp16 tensor-core GEMM: C[M,N] = A[M,K] @ W[N,K]^T + bias (+epi)
// CTA 128x128, 256 thr = 8 warps (2M x 4N), warp 64x32, K-chunk 32.
// SMEM: half tiles, row = 32 halves = 64B = 4 x 16B units,
// physical unit = unit ^ (row & 3)  (conflict-free for STS.64 + ldmatrix).
// A tile 8KB, B tile 8KB, double buffered = 32KB static smem.
// ====================================================================
template<int EPI>   // 0=none, 1=gelu, 2=+res
__global__ __launch_bounds__(256) void hgemm(
    const float* __restrict__ A, const float* __restrict__ W,
    const float* __restrict__ bias, const float* __restrict__ res,
    float* __restrict__ C, int N, int K)
{
    __shared__ __align__(16) char smh[2*16384];
    const int tid  = threadIdx.x;
    const int lane = tid & 31;
    const int wid  = tid >> 5;
    const int wm   = wid >> 2;
    const int wn   = wid & 3;
    const int bm = blockIdx.y * 128;
    const int bn = blockIdx.x * 128;
    const uint32_t sb = s2u(smh);

    const float* Ab = A + (size_t)bm * K;
    const float* Wb = W + (size_t)bn * K;

    float4 ar[4], br[4];

    auto LOAD = [&](int kbase) {
        #pragma unroll
        for (int i = 0; i < 4; i++) {
            int idx = i*256 + tid;
            int row = idx >> 3, seg = idx & 7;
            ar[i] = *(const float4*)(Ab + (size_t)row*K + kbase + seg*4);
            br[i] = *(const float4*)(Wb + (size_t)row*K + kbase + seg*4);
        }
    };
    auto STORE = [&](int buf) {
        char* As = smh + buf*16384;
        char* Bs = As + 8192;
        #pragma unroll
        for (int i = 0; i < 4; i++) {
            int idx = i*256 + tid;
            int row = idx >> 3, seg = idx & 7;
            uint32_t off = row*64 + (((seg>>1) ^ (row&3))*16) + (seg&1)*8;
            __half2 a0 = __floats2half2_rn(ar[i].x, ar[i].y);
            __half2 a1 = __floats2half2_rn(ar[i].z, ar[i].w);
            __half2 b0 = __floats2half2_rn(br[i].x, br[i].y);
            __half2 b1 = __floats2half2_rn(br[i].z, br[i].w);
            uint2 av = make_uint2(*(uint32_t*)&a0, *(uint32_t*)&a1);
            uint2 bv = make_uint2(*(uint32_t*)&b0, *(uint32_t*)&b1);
            *(uint2*)(As + off) = av;
            *(uint2*)(Bs + off) = bv;
        }
    };

    float acc[4][4][4];
    #pragma unroll
    for (int a = 0; a < 4; a++)
        #pragma unroll
        for (int b = 0; b < 4; b++)
            #pragma unroll
            for (int c = 0; c < 4; c++) acc[a][b][c] = 0.f;

    const int nk = K >> 5;
    LOAD(0);
    STORE(0);
    __syncthreads();

    const int lm = lane >> 3;   // ldmatrix sub-matrix id
    const int lr = lane & 7;

    for (int kt = 0; kt < nk; kt++) {
        int buf = kt & 1;
        if (kt + 1 < nk) LOAD((kt + 1) << 5);
        uint32_t Abase = sb + buf*16384;
        uint32_t Bbase = Abase + 8192;
        #pragma unroll
        for (int s = 0; s < 2; s++) {
            uint32_t af[4][4];
            #pragma unroll
            for (int mt = 0; mt < 4; mt++) {
                int row = wm*64 + mt*16 + (lm&1)*8 + lr;
                int unit = s*2 + (lm>>1);
                ldsm4(af[mt], Abase + row*64 + ((unit ^ (row&3))*16));
            }
            uint32_t bf[4][2];
            #pragma unroll
            for (int np = 0; np < 2; np++) {
                int nr = wn*32 + (np*2 + (lm>>1))*8 + lr;
                int unit = s*2 + (lm&1);
                uint32_t r[4];
                ldsm4(r, Bbase + nr*64 + ((unit ^ (nr&3))*16));
                bf[np*2][0] = r[0]; bf[np*2][1] = r[1];
                bf[np*2+1][0] = r[2]; bf[np*2+1][1] = r[3];
            }
            #pragma unroll
            for (int mt = 0; mt < 4; mt++)
                #pragma unroll
                for (int nt = 0; nt < 4; nt++)
                    mma_f16(acc[mt][nt], af[mt], bf[nt]);
        }
        if (kt + 1 < nk) {
            STORE(buf ^ 1);
            __syncthreads();
        }
    }

    const int g = lane >> 2, t = lane & 3;
    #pragma unroll
    for (int mt = 0; mt < 4; mt++) {
        int row0 = bm + wm*64 + mt*16 + g;
        #pragma unroll
        for (int nt = 0; nt < 4; nt++) {
            int col = bn + wn*32 + nt*8 + 2*t;
            float b0 = bias[col], b1 = bias[col+1];
            float v0 = acc[mt][nt][0] + b0;
            float v1 = acc[mt][nt][1] + b1;
            float v2 = acc[mt][nt][2] + b0;
            float v3 = acc[mt][nt][3] + b1;
            if (EPI == 1) {
                v0 = gelu_f(v0); v1 = gelu_f(v1); v2 = gelu_f(v2); v3 = gelu_f(v3);
            }
            if (EPI == 2) {
                const float* r0 = res + (size_t)row0*N + col;
                const float* r1 = res + (size_t)(row0+8)*N + col;
                v0 += r0[0]; v1 += r0[1]; v2 += r1[0]; v3 += r1[1];
            }
            *(float2*)&C[(size_t)row0*N + col]     = make_float2(v0, v1);
            *(float2*)&C[(size_t)(row0+8)*N + col] = make_float2(v2, v3);
        }
    }
}

// ---------------- layernorm: warp per row, 8 rows per block ----------------
__global__ __launch_bounds__(256) void lnw_kernel(const float* __restrict__ x,
        const float* __restrict__ g, const float* __restrict__ bb,
        float* __restrict__ out)
{
    int row  = blockIdx.x * 8 + (threadIdx.x >> 5);
    int lane = threadIdx.x & 31;
    const float4* xr = (const float4*)x + (size_t)row*(DD/4);
    float4 v[4];
    #pragma unroll
    for (int j = 0; j < 4; j++) v[j] = xr[lane + 32*j];
    float s = 0.f;
    #pragma unroll
    for (int j = 0; j < 4; j++) s += v[j].x + v[j].y + v[j].z + v[j].w;
    #pragma unroll
    for (int o = 16; o > 0; o >>= 1) s += __shfl_xor_sync(0xffffffffu, s, o);
    float mean = s * (1.0f/DD);
    float q = 0.f;
    #pragma unroll
    for (int j = 0; j < 4; j++) {
        float a = v[j].x-mean, b = v[j].y-mean, c = v[j].z-mean, d = v[j].w-mean;
        q += a*a + b*b + c*c + d*d;
    }
    #pragma unroll
    for (int o = 16; o > 0; o >>= 1) q += __shfl_xor_sync(0xffffffffu, q, o);
    float inv = rsqrtf(q * (1.0f/DD) + 1e-5f);
    float4* orow = (float4*)out + (size_t)row*(DD/4);
    #pragma unroll
    for (int j = 0; j < 4; j++) {
        float4 gg = ((const float4*)g)[lane + 32*j];
        float4 bv = ((const float4*)bb)[lane + 32*j];
        orow[lane + 32*j] = make_float4(
            (v[j].x-mean)*inv*gg.x + bv.x, (v[j].y-mean)*inv*gg.y + bv.y,
            (v[j].z-mean)*inv*gg.z + bv.z, (v[j].w-mean)*inv*gg.w + bv.w);
    }
}

// ---------------- column sums, two-stage deterministic ----------------
__global__ void colsum1_kernel(const float* __restrict__ xn, float* __restrict__ part)
{
    int b = blockIdx.y;
    int c = blockIdx.z;
    int d = blockIdx.x * 128 + threadIdx.x;
    const float* p = xn + (size_t)b*SS*DD + (size_t)c*128*DD + d;
    float s = 0.f;
    #pragma unroll 8
    for (int k = 0; k < 128; k++) s += p[(size_t)k*DD];
    part[((size_t)c*BB + b)*DD + d] = s;
}
__global__ void colsum2_kernel(const float* __restrict__ part, float* __restrict__ cs)
{
    int i = blockIdx.x * 256 + threadIdx.x;
    if (i < BB*DD) {
        float s = 0.f;
        #pragma unroll
        for (int c = 0; c < 16; c++) s += part[(size_t)c*BB*DD + i];
        cs[i] = s;
    }
}

// ---------------- sparsity: warp per row; fp32 two-prod + double reduce ----
__global__ __launch_bounds__(256) void sparsw_kernel(const float* __restrict__ xn,
        const float* __restrict__ cs, float* __restrict__ sp)
{
    int row  = blockIdx.x * 8 + (threadIdx.x >> 5);
    int lane = threadIdx.x & 31;
    int b = row >> 11;
    const float4* xr = (const float4*)xn + (size_t)row*(DD/4);
    const float4* cr = (const float4*)cs + b*(DD/4);
    float dp = 0.f, de = 0.f, mp = 0.f, me = 0.f;
    #pragma unroll
    for (int j = 0; j < 4; j++) {
        float4 v = xr[lane + 32*j];
        float4 c = cr[lane + 32*j];
        float vv[4] = {v.x, v.y, v.z, v.w};
        float cc[4] = {c.x, c.y, c.z, c.w};
        #pragma unroll
        for (int e = 0; e < 4; e++) {
            float p = vv[e]*vv[e];
            de += fmaf(vv[e], vv[e], -p);
            dp += p;
            float q = vv[e]*cc[e];
            me += fmaf(vv[e], cc[e], -q);
            mp += q;
        }
    }
    double dd = (double)dp + (double)de;
    double dm = (double)mp + (double)me;
    #pragma unroll
    for (int o = 16; o > 0; o >>= 1) {
        dd += __shfl_xor_sync(0xffffffffu, dd, o);
        dm += __shfl_xor_sync(0xffffffffu, dm, o);
    }
    if (lane == 0)
        sp[row] = (float)((dd - dm * (1.0/SS)) * 0.04419417382415922);
}

// ---------------- top-39 ----------------
__global__ __launch_bounds__(256) void topk_kernel(const float* __restrict__ sp,
        int* __restrict__ tidx)
{
    int b = blockIdx.x;
    int t = threadIdx.x;
    __shared__ float sv[SS];
    __shared__ float rbv[8];
    __shared__ int   rbi[8];
    for (int i = t; i < SS; i += 256) sv[i] = sp[b*SS + i];
    __syncthreads();
    for (int sel = 0; sel < TOPQ; ++sel) {
        float bv = -3.0e38f; int bi = 0;
        for (int i = t; i < SS; i += 256) {
            float v = sv[i];
            if (v > bv || (v == bv && i < bi)) { bv = v; bi = i; }
        }
        #pragma unroll
        for (int o = 16; o > 0; o >>= 1) {
            float ov = __shfl_down_sync(0xffffffffu, bv, o);
            int   oi = __shfl_down_sync(0xffffffffu, bi, o);
            if (ov > bv || (ov == bv && oi < bi)) { bv = ov; bi = oi; }
        }
        if ((t & 31) == 0) { rbv[t >> 5] = bv; rbi[t >> 5] = bi; }
        __syncthreads();
        if (t == 0) {
            float fv = rbv[0]; int fi = rbi[0];
            #pragma unroll
            for (int w = 1; w < 8; w++)
                if (rbv[w] > fv || (rbv[w] == fv && rbi[w] < fi)) { fv = rbv[w]; fi = rbi[w]; }
            tidx[b*TOPQ + sel] = fi;
            sv[fi] = -3.4e38f;
        }
        __syncthreads();
    }
}

// ---------------- small row projection (optional gather / partial-sum src) --
__global__ __launch_bounds__(256) void rowproj_kernel(const float* __restrict__ src,
        const int* __restrict__ gidx, const float* __restrict__ part,
        const float* __restrict__ W, const float* __restrict__ bias,
        float* __restrict__ out)
{
    int r = blockIdx.x;
    __shared__ float xr[DD];
    if (part) {
        const int N4 = BB*TOPQ*DD/4;
        const float4* p = (const float4*)part;
        for (int i = threadIdx.x; i < DD/4; i += 256) {
            int idx = r*(DD/4) + i;
            float4 a = p[idx], b = p[idx+N4], c = p[idx+2*N4], d = p[idx+3*N4];
            ((float4*)xr)[i] = make_float4(a.x+b.x+c.x+d.x, a.y+b.y+c.y+d.y,
                                           a.z+b.z+c.z+d.z, a.w+b.w+c.w+d.w);
        }
    } else {
        const float* srow;
        if (gidx) { int b = r / TOPQ; srow = src + ((size_t)b*SS + gidx[r]) * DD; }
        else        srow = src + (size_t)r * DD;
        for (int i = threadIdx.x; i < DD/4; i += 256)
            ((float4*)xr)[i] = ((const float4*)srow)[i];
    }
    __syncthreads();
    for (int j = threadIdx.x; j < DD; j += 256) {
        const float4* w4 = (const float4*)(W + (size_t)j*DD);
        float acc = 0.f;
        #pragma unroll 4
        for (int k = 0; k < DD/4; k++) {
            float4 w = w4[k]; float4 xv = ((float4*)xr)[k];
            acc = fmaf(w.x, xv.x, fmaf(w.y, xv.y, fmaf(w.z, xv.z, fmaf(w.w, xv.w, acc))));
        }
        out[(size_t)r*DD + j] = acc + bias[j];
    }
}

// ---------------- attention: scores (K-tiled, shared across queries) --------
__global__ __launch_bounds__(256) void scorek_kernel(const float* __restrict__ qs,
        const float* __restrict__ kv, float* __restrict__ sc)
{
    int kt = blockIdx.x, h = blockIdx.y, b = blockIdx.z;
    __shared__ float Qt[DH][TOPQ+1];
    __shared__ float Ks[128][DH];
    int tid = threadIdx.x;
    for (int i = tid; i < TOPQ*DH; i += 256) {
        int q = i % TOPQ, d = i / TOPQ;
        Qt[d][q] = qs[((size_t)(b*TOPQ+q))*DD + h*DH + d];
    }
    for (int i = tid; i < 128*16; i += 256) {
        int row = i >> 4, c4 = i & 15;
        *(float4*)&Ks[row][c4*4] =
            *(const float4*)(kv + ((size_t)(b*SS + kt*128 + row))*(2*DD) + h*DH + c4*4);
    }
    __syncthreads();
    for (int p = tid; p < TOPQ*128; p += 256) {
        int q = p % TOPQ, k = p / TOPQ;
        float a = 0.f;
        #pragma unroll 8
        for (int d = 0; d < DH; d++) a = fmaf(Qt[d][q], Ks[k][d], a);
        sc[((size_t)(b*HH+h)*TOPQ + q)*SS + kt*128 + k] = a * 0.125f;
    }
}

// ---------------- attention: row softmax (in place, normalized) --------------
__global__ __launch_bounds__(256) void softmax_kernel(float* __restrict__ sc)
{
    size_t base = (size_t)blockIdx.x * SS;
    int t = threadIdx.x;
    float4* p = (float4*)(sc + base);
    float4 v0 = p[t], v1 = p[t + 256];
    __shared__ float red[8];
    float m = fmaxf(fmaxf(fmaxf(v0.x, v0.y), fmaxf(v0.z, v0.w)),
                    fmaxf(fmaxf(v1.x, v1.y), fmaxf(v1.z, v1.w)));
    #pragma unroll
    for (int o = 16; o > 0; o >>= 1) m = fmaxf(m, __shfl_down_sync(0xffffffffu, m, o));
    if ((t & 31) == 0) red[t >> 5] = m;
    __syncthreads();
    m = red[0];
    #pragma unroll
    for (int w = 1; w < 8; w++) m = fmaxf(m, red[w]);
    __syncthreads();
    v0.x = __expf(v0.x - m); v0.y = __expf(v0.y - m);
    v0.z = __expf(v0.z - m); v0.w = __expf(v0.w - m);
    v1.x = __expf(v1.x - m); v1.y = __expf(v1.y - m);
    v1.z = __expf(v1.z - m); v1.w = __expf(v1.w - m);
    float s = v0.x+v0.y+v0.z+v0.w + v1.x+v1.y+v1.z+v1.w;
    #pragma unroll
    for (int o = 16; o > 0; o >>= 1) s += __shfl_down_sync(0xffffffffu, s, o);
    if ((t & 31) == 0) red[t >> 5] = s;
    __syncthreads();
    float tot = red[0]+red[1]+red[2]+red[3]+red[4]+red[5]+red[6]+red[7];
    float inv = 1.0f / tot;
    v0.x*=inv; v0.y*=inv; v0.z*=inv; v0.w*=inv;
    v1.x*=inv; v1.y*=inv; v1.z*=inv; v1.w*=inv;
    p[t] = v0; p[t + 256] = v1;
}

// ---------------- attention: probs @ V (k-split partials) --------------------
__global__ __launch_bounds__(256) void ctxv_kernel(const float* __restrict__ pr_g,
        const float* __restrict__ kv, float* __restrict__ part)
{
    int g = blockIdx.x, h = blockIdx.y, b = blockIdx.z;
    __shared__ float Vt[64][64];
    __shared__ float Pt[TOPQ][64];
    int tid = threadIdx.x, w = tid >> 5, lid = tid & 31;
    float acc[5][2];
    #pragma unroll
    for (int i = 0; i < 5; i++) { acc[i][0] = 0.f; acc[i][1] = 0.f; }
    for (int t = 0; t < 8; t++) {
        int k0 = g * 512 + t * 64;
        for (int i = tid; i < 64*16; i += 256) {
            int row = i >> 4, c4 = i & 15;
            *(float4*)&Vt[row][c4*4] =
                *(const float4*)(kv + ((size_t)(b*SS + k0 + row))*(2*DD) + DD + h*DH + c4*4);
        }
        for (int i = tid; i < TOPQ*64; i += 256) {
            int q = i >> 6, kk = i & 63;
            Pt[q][kk] = pr_g[((size_t)(b*HH+h)*TOPQ + q)*SS + k0 + kk];
        }
        __syncthreads();
        int ii = 0;
        for (int q = w; q < TOPQ; q += 8, ii++) {
            float a0 = acc[ii][0], a1 = acc[ii][1];
            #pragma unroll 8
            for (int kk = 0; kk < 64; kk++) {
                float2 v = *(float2*)&Vt[kk][2*lid];
                float pp = Pt[q][kk];
                a0 = fmaf(pp, v.x, a0); a1 = fmaf(pp, v.y, a1);
            }
            acc[ii][0] = a0; acc[ii][1] = a1;
        }
        __syncthreads();
    }
    int ii = 0;
    for (int q = w; q < TOPQ; q += 8, ii++) {
        float* dst = part + (size_t)g*(BB*TOPQ*DD) + ((size_t)(b*TOPQ+q))*DD + h*DH + 2*lid;
        *(float2*)dst = make_float2(acc[ii][0], acc[ii][1]);
    }
}

// ---------------- x2 = x + base ----------------
__global__ void addbase_kernel(const float* __restrict__ x,
        const float* __restrict__ cs, float* __restrict__ x2)
{
    size_t i = (size_t)blockIdx.x * blockDim.x + threadIdx.x;
    int col4 = (int)(i & 127);
    int row  = (int)(i >> 7);
    int b    = row >> 11;
    float4 xv = ((const float4*)x)[i];
    float4 c  = ((const float4*)cs)[b*(DD/4) + col4];
    const float r = 1.0f / SS;
    ((float4*)x2)[i] = make_float4(xv.x + c.x*r, xv.y + c.y*r, xv.z + c.z*r, xv.w + c.w*r);
}

// ---------------- scatter sparse rows ----------------
__global__ __launch_bounds__(128) void scatter_kernel(const float* __restrict__ x,
        const float* __restrict__ aout, const int* __restrict__ tidx,
        float* __restrict__ x2)
{
    int r = blockIdx.x;
    int b = r / TOPQ;
    int srow = b*SS + tidx[r];
    int t = threadIdx.x;
    float4 xv = ((const float4*)x)[(size_t)srow*(DD/4) + t];
    float4 a  = ((const float4*)aout)[(size_t)r*(DD/4) + t];
    ((float4*)x2)[(size_t)srow*(DD/4) + t] =
        make_float4(xv.x + a.x, xv.y + a.y, xv.z + a.z, xv.w + a.w);
}

// ---------------- ratio tail ----------------
__global__ void ratio_kernel(float* out, int out_size)
{
    int i = NROWS*DD + blockIdx.x*blockDim.x + threadIdx.x;
    if (i < out_size) out[i] = (float)TOPQ / (float)SS;
}

// ---------------- launch ----------------
extern "C" void kernel_launch(void* const* d_in, const int* in_sizes, int n_in,
                              void* d_out, int out_size)
{
    const float* x    = (const float*)d_in[0];
    const float* ln1g = (const float*)d_in[1];
    const float* ln1b = (const float*)d_in[2];
    const float* in_w = (const float*)d_in[3];
    const float* in_b = (const float*)d_in[4];
    const float* outw = (const float*)d_in[5];
    const float* outb = (const float*)d_in[6];
    const float* ln2g = (const float*)d_in[7];
    const float* ln2b = (const float*)d_in[8];
    const float* w1   = (const float*)d_in[9];
    const float* b1   = (const float*)d_in[10];
    const float* w2   = (const float*)d_in[11];
    const float* b2   = (const float*)d_in[12];
    float* out = (float*)d_out;

    float *xn, *x2, *xn2, *kv, *h1, *cs, *csp, *sp, *qs, *ctxp, *aout, *scores;
    int *tidx;
    cudaGetSymbolAddress((void**)&xn,    g_xn);
    cudaGetSymbolAddress((void**)&x2,    g_x2);
    cudaGetSymbolAddress((void**)&xn2,   g_xn2);
    cudaGetSymbolAddress((void**)&kv,    g_kv);
    cudaGetSymbolAddress((void**)&h1,    g_h1);
    cudaGetSymbolAddress((void**)&cs,    g_cs);
    cudaGetSymbolAddress((void**)&csp,   g_cspart);
    cudaGetSymbolAddress((void**)&sp,    g_sp);
    cudaGetSymbolAddress((void**)&qs,    g_qs);
    cudaGetSymbolAddress((void**)&ctxp,  g_ctxp);
    cudaGetSymbolAddress((void**)&aout,  g_aout);
    cudaGetSymbolAddress((void**)&scores,g_scores);
    cudaGetSymbolAddress((void**)&tidx,  g_tidx);

    // 1) layernorm1 (warp-per-row)
    lnw_kernel<<<NROWS/8, 256>>>(x, ln1g, ln1b, xn);
    // 2) column sums (deterministic two-stage)
    colsum1_kernel<<<dim3(DD/128, BB, 16), 128>>>(xn, csp);
    colsum2_kernel<<<(BB*DD + 255)/256, 256>>>(csp, cs);
    // 3) analytic sparsity (warp-per-row, compensated fp32 -> double reduce)
    sparsw_kernel<<<NROWS/8, 256>>>(xn, cs, sp);
    // 4) top-39 per batch
    topk_kernel<<<BB, 256>>>(sp, tidx);
    // 5) gather + Q projection
    rowproj_kernel<<<BB*TOPQ, 256>>>(xn, tidx, nullptr, in_w, in_b, qs);
    // 6) fused K+V projection (fp16 mma + ldmatrix)
    hgemm<0><<<dim3((2*DD)/128, NROWS/128), 256>>>(
        xn, in_w + (size_t)DD*DD, in_b + DD, nullptr, kv, 2*DD, DD);
    // 7) attention: scores -> softmax -> probs@V
    scorek_kernel<<<dim3(SS/128, HH, BB), 256>>>(qs, kv, scores);
    softmax_kernel<<<BB*HH*TOPQ, 256>>>(scores);
    ctxv_kernel<<<dim3(4, HH, BB), 256>>>(scores, kv, ctxp);
    // 8) output projection (partial-sum source fused in)
    rowproj_kernel<<<BB*TOPQ, 256>>>(nullptr, nullptr, ctxp, outw, outb, aout);
    // 9) residual: base everywhere, sparse rows overwritten
    addbase_kernel<<<(NROWS*(DD/4))/256, 256>>>(x, cs, x2);
    scatter_kernel<<<BB*TOPQ, 128>>>(x, aout, tidx, x2);
    // 10) layernorm2
    lnw_kernel<<<NROWS/8, 256>>>(x2, ln2g, ln2b, xn2);
    // 11) FFN (fp16 mma + ldmatrix)
    hgemm<1><<<dim3(FF_/128, NROWS/128), 256>>>(
        xn2, w1, b1, nullptr, h1, FF_, DD);
    hgemm<2><<<dim3(DD/128, NROWS/128), 256>>>(
        h1, w2, b2, x2, out, DD, FF_);
    // 12) ratio tail
    if (out_size > NROWS*DD) {
        int tail = out_size - NROWS*DD;
        ratio_kernel<<<(tail + 255)/256, 256>>>(out, out_size);
    }
}

// round 5
// speedup vs baseline: 3.0826x; 1.2507x over previous
#include <cuda_runtime.h>
#include <cuda_fp16.h>
#include <math.h>
#include <stdint.h>

#define BB 8
#define SS 2048
#define DD 512
#define FF_ 2048
#define HH 8
#define DH 64
#define TOPQ 39
#define NROWS (BB*SS)   /* 16384 */

// ---------------- static scratch ----------------
__device__ float g_xn  [NROWS*DD];
__device__ float g_x2  [NROWS*DD];
__device__ float g_kv  [NROWS*2*DD];
__device__ float g_cs  [BB*DD];
__device__ float g_cspart[16*BB*DD];
__device__ float g_sp  [BB*SS];
__device__ int   g_tidx[BB*TOPQ];
__device__ float g_qs  [BB*TOPQ*DD];
__device__ float g_ctxp[4*BB*TOPQ*DD];
__device__ float g_aout[BB*TOPQ*DD];
__device__ float g_scores[(size_t)BB*HH*TOPQ*SS];
// fp16 operand copies
__device__ __half g_xn16 [NROWS*DD];
__device__ __half g_xn2h [NROWS*DD];
__device__ __half g_h1h  [(size_t)NROWS*FF_];
__device__ __half g_wkv16[2*DD*DD];
__device__ __half g_w1h  [FF_*DD];
__device__ __half g_w2h  [DD*FF_];

// ---------------- helpers ----------------
__device__ __forceinline__ uint32_t s2u(const void* p) {
    uint32_t a;
    asm("{ .reg .u64 t; cvta.to.shared.u64 t, %1; cvt.u32.u64 %0, t; }" : "=r"(a) : "l"(p));
    return a;
}
__device__ __forceinline__ void mma_f16(float* d, const uint32_t* a, const uint32_t* b) {
    asm volatile("mma.sync.aligned.m16n8k16.row.col.f32.f16.f16.f32 "
        "{%0,%1,%2,%3}, {%4,%5,%6,%7}, {%8,%9}, {%0,%1,%2,%3};"
        : "+f"(d[0]), "+f"(d[1]), "+f"(d[2]), "+f"(d[3])
        : "r"(a[0]), "r"(a[1]), "r"(a[2]), "r"(a[3]), "r"(b[0]), "r"(b[1]));
}
__device__ __forceinline__ void ldsm4(uint32_t* r, uint32_t addr) {
    asm volatile("ldmatrix.sync.aligned.m8n8.x4.shared.b16 {%0,%1,%2,%3}, [%4];"
        : "=r"(r[0]), "=r"(r[1]), "=r"(r[2]), "=r"(r[3]) : "r"(addr));
}
__device__ __forceinline__ void cpa16(uint32_t dst, const void* src) {
    asm volatile("cp.async.cg.shared.global [%0], [%1], 16;" :: "r"(dst), "l"(src));
}
__device__ __forceinline__ void cpcommit() {
    asm volatile("cp.async.commit_group;" ::: "memory");
}
template<int N> __device__ __forceinline__ void cpwait() {
    asm volatile("cp.async.wait_group %0;" :: "n"(N) : "memory");
}
__device__ __forceinline__ float gelu_f(float x) {
    return 0.5f * x * (1.0f + erff(x * 0.7071067811865476f));
}

// ====================================================================
// fp16 GEMM, fp16 operands in gmem, cp.async pipeline.
// C[M,N] = A[M,K] @ W[N,K]^T + bias (+epi). CTA 128x128, K-chunk 32,
// 256 thr = 8 warps (2M x 4N), warp 64x32, 2-stage cp.async, 2 CTAs/SM.
// SMEM layout per tile: row (128) x 64B; 16B unit u at phys (u ^ (row&3)).
// ====================================================================
template<int EPI, typename OutT>   // EPI: 0=none, 1=gelu, 2=+res
__global__ __launch_bounds__(256, 2) void hgemm(
    const __half* __restrict__ A, const __half* __restrict__ W,
    const float* __restrict__ bias, const float* __restrict__ res,
    OutT* __restrict__ C, int N, int K)
{
    __shared__ __align__(16) char smh[2*16384];
    const int tid  = threadIdx.x;
    const int lane = tid & 31;
    const int wid  = tid >> 5;
    const int wm   = wid >> 2;
    const int wn   = wid & 3;
    const int bm = blockIdx.y * 128;
    const int bn = blockIdx.x * 128;
    const uint32_t sb = s2u(smh);

    const __half* Ab = A + (size_t)bm * K;
    const __half* Wb = W + (size_t)bn * K;

    const int crow = tid >> 2;          // 0..63? no: tid>>2 -> 0..63. Need idx loop.
    (void)crow;

    auto ISSUE = [&](int buf, int kbase) {
        #pragma unroll
        for (int i = 0; i < 2; i++) {
            int idx = i*256 + tid;           // 0..511
            int row = idx >> 2, unit = idx & 3;
            uint32_t off = row*64 + ((unit ^ (row&3))*16);
            cpa16(sb + buf*16384 + off,        Ab + (size_t)row*K + kbase + unit*8);
            cpa16(sb + buf*16384 + 8192 + off, Wb + (size_t)row*K + kbase + unit*8);
        }
        cpcommit();
    };

    float acc[4][4][4];
    #pragma unroll
    for (int a = 0; a < 4; a++)
        #pragma unroll
        for (int b = 0; b < 4; b++)
            #pragma unroll
            for (int c = 0; c < 4; c++) acc[a][b][c] = 0.f;

    const int nk = K >> 5;
    const int lm = lane >> 3;
    const int lr = lane & 7;

    ISSUE(0, 0);
    for (int kt = 0; kt < nk; kt++) {
        int buf = kt & 1;
        if (kt + 1 < nk) { ISSUE(buf ^ 1, (kt + 1) << 5); cpwait<1>(); }
        else             { cpwait<0>(); }
        __syncthreads();
        uint32_t Abase = sb + buf*16384;
        uint32_t Bbase = Abase + 8192;
        #pragma unroll
        for (int s = 0; s < 2; s++) {
            uint32_t af[4][4];
            #pragma unroll
            for (int mt = 0; mt < 4; mt++) {
                int row = wm*64 + mt*16 + (lm&1)*8 + lr;
                int unit = s*2 + (lm>>1);
                ldsm4(af[mt], Abase + row*64 + ((unit ^ (row&3))*16));
            }
            uint32_t bf[4][2];
            #pragma unroll
            for (int np = 0; np < 2; np++) {
                int nr = wn*32 + (np*2 + (lm>>1))*8 + lr;
                int unit = s*2 + (lm&1);
                uint32_t r[4];
                ldsm4(r, Bbase + nr*64 + ((unit ^ (nr&3))*16));
                bf[np*2][0] = r[0]; bf[np*2][1] = r[1];
                bf[np*2+1][0] = r[2]; bf[np*2+1][1] = r[3];
            }
            #pragma unroll
            for (int mt = 0; mt < 4; mt++)
                #pragma unroll
                for (int nt = 0; nt < 4; nt++)
                    mma_f16(acc[mt][nt], af[mt], bf[nt]);
        }
        __syncthreads();
    }

    const int g = lane >> 2, t = lane & 3;
    #pragma unroll
    for (int mt = 0; mt < 4; mt++) {
        int row0 = bm + wm*64 + mt*16 + g;
        #pragma unroll
        for (int nt = 0; nt < 4; nt++) {
            int col = bn + wn*32 + nt*8 + 2*t;
            float b0 = bias[col], b1 = bias[col+1];
            float v0 = acc[mt][nt][0] + b0;
            float v1 = acc[mt][nt][1] + b1;
            float v2 = acc[mt][nt][2] + b0;
            float v3 = acc[mt][nt][3] + b1;
            if (EPI == 1) {
                v0 = gelu_f(v0); v1 = gelu_f(v1); v2 = gelu_f(v2); v3 = gelu_f(v3);
            }
            if (EPI == 2) {
                const float* r0 = res + (size_t)row0*N + col;
                const float* r1 = res + (size_t)(row0+8)*N + col;
                v0 += r0[0]; v1 += r0[1]; v2 += r1[0]; v3 += r1[1];
            }
            if constexpr (sizeof(OutT) == 2) {
                *(__half2*)&C[(size_t)row0*N + col]     = __floats2half2_rn(v0, v1);
                *(__half2*)&C[(size_t)(row0+8)*N + col] = __floats2half2_rn(v2, v3);
            } else {
                *(float2*)&C[(size_t)row0*N + col]     = make_float2(v0, v1);
                *(float2*)&C[(size_t)(row0+8)*N + col] = make_float2(v2, v3);
            }
        }
    }
}

// ---------------- fp32 -> fp16 bulk convert ----------------
__global__ void f2h_kernel(const float* __restrict__ src, __half* __restrict__ dst, int n4)
{
    int i = blockIdx.x * 256 + threadIdx.x;
    if (i < n4) {
        float4 v = ((const float4*)src)[i];
        __half2 h0 = __floats2half2_rn(v.x, v.y);
        __half2 h1 = __floats2half2_rn(v.z, v.w);
        ((__half2*)dst)[2*i]   = h0;
        ((__half2*)dst)[2*i+1] = h1;
    }
}

// ---------------- layernorm: warp per row; fp32 out optional, fp16 out opt --
__global__ __launch_bounds__(256) void lnw_kernel(const float* __restrict__ x,
        const float* __restrict__ g, const float* __restrict__ bb,
        float* __restrict__ out, __half* __restrict__ out16)
{
    int row  = blockIdx.x * 8 + (threadIdx.x >> 5);
    int lane = threadIdx.x & 31;
    const float4* xr = (const float4*)x + (size_t)row*(DD/4);
    float4 v[4];
    #pragma unroll
    for (int j = 0; j < 4; j++) v[j] = xr[lane + 32*j];
    float s = 0.f;
    #pragma unroll
    for (int j = 0; j < 4; j++) s += v[j].x + v[j].y + v[j].z + v[j].w;
    #pragma unroll
    for (int o = 16; o > 0; o >>= 1) s += __shfl_xor_sync(0xffffffffu, s, o);
    float mean = s * (1.0f/DD);
    float q = 0.f;
    #pragma unroll
    for (int j = 0; j < 4; j++) {
        float a = v[j].x-mean, b = v[j].y-mean, c = v[j].z-mean, d = v[j].w-mean;
        q += a*a + b*b + c*c + d*d;
    }
    #pragma unroll
    for (int o = 16; o > 0; o >>= 1) q += __shfl_xor_sync(0xffffffffu, q, o);
    float inv = rsqrtf(q * (1.0f/DD) + 1e-5f);
    #pragma unroll
    for (int j = 0; j < 4; j++) {
        float4 gg = ((const float4*)g)[lane + 32*j];
        float4 bv = ((const float4*)bb)[lane + 32*j];
        float4 o4 = make_float4(
            (v[j].x-mean)*inv*gg.x + bv.x, (v[j].y-mean)*inv*gg.y + bv.y,
            (v[j].z-mean)*inv*gg.z + bv.z, (v[j].w-mean)*inv*gg.w + bv.w);
        if (out) ((float4*)out)[(size_t)row*(DD/4) + lane + 32*j] = o4;
        if (out16) {
            __half2 h0 = __floats2half2_rn(o4.x, o4.y);
            __half2 h1 = __floats2half2_rn(o4.z, o4.w);
            int base = (int)(lane + 32*j);
            ((__half2*)(out16 + (size_t)row*DD))[2*base]   = h0;
            ((__half2*)(out16 + (size_t)row*DD))[2*base+1] = h1;
        }
    }
}

// ---------------- column sums, two-stage deterministic ----------------
__global__ void colsum1_kernel(const float* __restrict__ xn, float* __restrict__ part)
{
    int b = blockIdx.y;
    int c = blockIdx.z;
    int d = blockIdx.x * 128 + threadIdx.x;
    const float* p = xn + (size_t)b*SS*DD + (size_t)c*128*DD + d;
    float s = 0.f;
    #pragma unroll 8
    for (int k = 0; k < 128; k++) s += p[(size_t)k*DD];
    part[((size_t)c*BB + b)*DD + d] = s;
}
__global__ void colsum2_kernel(const float* __restrict__ part, float* __restrict__ cs)
{
    int i = blockIdx.x * 256 + threadIdx.x;
    if (i < BB*DD) {
        float s = 0.f;
        #pragma unroll
        for (int c = 0; c < 16; c++) s += part[(size_t)c*BB*DD + i];
        cs[i] = s;
    }
}

// ---------------- sparsity: warp per row; compensated fp32 -> double -------
__global__ __launch_bounds__(256) void sparsw_kernel(const float* __restrict__ xn,
        const float* __restrict__ cs, float* __restrict__ sp)
{
    int row  = blockIdx.x * 8 + (threadIdx.x >> 5);
    int lane = threadIdx.x & 31;
    int b = row >> 11;
    const float4* xr = (const float4*)xn + (size_t)row*(DD/4);
    const float4* cr = (const float4*)cs + b*(DD/4);
    float dp = 0.f, de = 0.f, mp = 0.f, me = 0.f;
    #pragma unroll
    for (int j = 0; j < 4; j++) {
        float4 v = xr[lane + 32*j];
        float4 c = cr[lane + 32*j];
        float vv[4] = {v.x, v.y, v.z, v.w};
        float cc[4] = {c.x, c.y, c.z, c.w};
        #pragma unroll
        for (int e = 0; e < 4; e++) {
            float p = vv[e]*vv[e];
            de += fmaf(vv[e], vv[e], -p);
            dp += p;
            float q = vv[e]*cc[e];
            me += fmaf(vv[e], cc[e], -q);
            mp += q;
        }
    }
    double dd = (double)dp + (double)de;
    double dm = (double)mp + (double)me;
    #pragma unroll
    for (int o = 16; o > 0; o >>= 1) {
        dd += __shfl_xor_sync(0xffffffffu, dd, o);
        dm += __shfl_xor_sync(0xffffffffu, dm, o);
    }
    if (lane == 0)
        sp[row] = (float)((dd - dm * (1.0/SS)) * 0.04419417382415922);
}

// ---------------- top-39 ----------------
__global__ __launch_bounds__(256) void topk_kernel(const float* __restrict__ sp,
        int* __restrict__ tidx)
{
    int b = blockIdx.x;
    int t = threadIdx.x;
    __shared__ float sv[SS];
    __shared__ float rbv[8];
    __shared__ int   rbi[8];
    for (int i = t; i < SS; i += 256) sv[i] = sp[b*SS + i];
    __syncthreads();
    for (int sel = 0; sel < TOPQ; ++sel) {
        float bv = -3.0e38f; int bi = 0;
        for (int i = t; i < SS; i += 256) {
            float v = sv[i];
            if (v > bv || (v == bv && i < bi)) { bv = v; bi = i; }
        }
        #pragma unroll
        for (int o = 16; o > 0; o >>= 1) {
            float ov = __shfl_down_sync(0xffffffffu, bv, o);
            int   oi = __shfl_down_sync(0xffffffffu, bi, o);
            if (ov > bv || (ov == bv && oi < bi)) { bv = ov; bi = oi; }
        }
        if ((t & 31) == 0) { rbv[t >> 5] = bv; rbi[t >> 5] = bi; }
        __syncthreads();
        if (t == 0) {
            float fv = rbv[0]; int fi = rbi[0];
            #pragma unroll
            for (int w = 1; w < 8; w++)
                if (rbv[w] > fv || (rbv[w] == fv && rbi[w] < fi)) { fv = rbv[w]; fi = rbi[w]; }
            tidx[b*TOPQ + sel] = fi;
            sv[fi] = -3.4e38f;
        }
        __syncthreads();
    }
}

// ---------------- small row projection (gather / partial-sum src) ----------
__global__ __launch_bounds__(256) void rowproj_kernel(const float* __restrict__ src,
        const int* __restrict__ gidx, const float* __restrict__ part,
        const float* __restrict__ W, const float* __restrict__ bias,
        float* __restrict__ out)
{
    int r = blockIdx.x;
    __shared__ float xr[DD];
    if (part) {
        const int N4 = BB*TOPQ*DD/4;
        const float4* p = (const float4*)part;
        for (int i = threadIdx.x; i < DD/4; i += 256) {
            int idx = r*(DD/4) + i;
            float4 a = p[idx], b = p[idx+N4], c = p[idx+2*N4], d = p[idx+3*N4];
            ((float4*)xr)[i] = make_float4(a.x+b.x+c.x+d.x, a.y+b.y+c.y+d.y,
                                           a.z+b.z+c.z+d.z, a.w+b.w+c.w+d.w);
        }
    } else {
        const float* srow;
        if (gidx) { int b = r / TOPQ; srow = src + ((size_t)b*SS + gidx[r]) * DD; }
        else        srow = src + (size_t)r * DD;
        for (int i = threadIdx.x; i < DD/4; i += 256)
            ((float4*)xr)[i] = ((const float4*)srow)[i];
    }
    __syncthreads();
    for (int j = threadIdx.x; j < DD; j += 256) {
        const float4* w4 = (const float4*)(W + (size_t)j*DD);
        float acc = 0.f;
        #pragma unroll 4
        for (int k = 0; k < DD/4; k++) {
            float4 w = w4[k]; float4 xv = ((float4*)xr)[k];
            acc = fmaf(w.x, xv.x, fmaf(w.y, xv.y, fmaf(w.z, xv.z, fmaf(w.w, xv.w, acc))));
        }
        out[(size_t)r*DD + j] = acc + bias[j];
    }
}

// ---------------- attention: scores ----------------
__global__ __launch_bounds__(256) void scorek_kernel(const float* __restrict__ qs,
        const float* __restrict__ kv, float* __restrict__ sc)
{
    int kt = blockIdx.x, h = blockIdx.y, b = blockIdx.z;
    __shared__ float Qt[DH][TOPQ+1];
    __shared__ float Ks[128][DH];
    int tid = threadIdx.x;
    for (int i = tid; i < TOPQ*DH; i += 256) {
        int q = i % TOPQ, d = i / TOPQ;
        Qt[d][q] = qs[((size_t)(b*TOPQ+q))*DD + h*DH + d];
    }
    for (int i = tid; i < 128*16; i += 256) {
        int row = i >> 4, c4 = i & 15;
        *(float4*)&Ks[row][c4*4] =
            *(const float4*)(kv + ((size_t)(b*SS + kt*128 + row))*(2*DD) + h*DH + c4*4);
    }
    __syncthreads();
    for (int p = tid; p < TOPQ*128; p += 256) {
        int q = p % TOPQ, k = p / TOPQ;
        float a = 0.f;
        #pragma unroll 8
        for (int d = 0; d < DH; d++) a = fmaf(Qt[d][q], Ks[k][d], a);
        sc[((size_t)(b*HH+h)*TOPQ + q)*SS + kt*128 + k] = a * 0.125f;
    }
}

// ---------------- attention: row softmax ----------------
__global__ __launch_bounds__(256) void softmax_kernel(float* __restrict__ sc)
{
    size_t base = (size_t)blockIdx.x * SS;
    int t = threadIdx.x;
    float4* p = (float4*)(sc + base);
    float4 v0 = p[t], v1 = p[t + 256];
    __shared__ float red[8];
    float m = fmaxf(fmaxf(fmaxf(v0.x, v0.y), fmaxf(v0.z, v0.w)),
                    fmaxf(fmaxf(v1.x, v1.y), fmaxf(v1.z, v1.w)));
    #pragma unroll
    for (int o = 16; o > 0; o >>= 1) m = fmaxf(m, __shfl_down_sync(0xffffffffu, m, o));
    if ((t & 31) == 0) red[t >> 5] = m;
    __syncthreads();
    m = red[0];
    #pragma unroll
    for (int w = 1; w < 8; w++) m = fmaxf(m, red[w]);
    __syncthreads();
    v0.x = __expf(v0.x - m); v0.y = __expf(v0.y - m);
    v0.z = __expf(v0.z - m); v0.w = __expf(v0.w - m);
    v1.x = __expf(v1.x - m); v1.y = __expf(v1.y - m);
    v1.z = __expf(v1.z - m); v1.w = __expf(v1.w - m);
    float s = v0.x+v0.y+v0.z+v0.w + v1.x+v1.y+v1.z+v1.w;
    #pragma unroll
    for (int o = 16; o > 0; o >>= 1) s += __shfl_down_sync(0xffffffffu, s, o);
    if ((t & 31) == 0) red[t >> 5] = s;
    __syncthreads();
    float tot = red[0]+red[1]+red[2]+red[3]+red[4]+red[5]+red[6]+red[7];
    float inv = 1.0f / tot;
    v0.x*=inv; v0.y*=inv; v0.z*=inv; v0.w*=inv;
    v1.x*=inv; v1.y*=inv; v1.z*=inv; v1.w*=inv;
    p[t] = v0; p[t + 256] = v1;
}

// ---------------- attention: probs @ V ----------------
__global__ __launch_bounds__(256) void ctxv_kernel(const float* __restrict__ pr_g,
        const float* __restrict__ kv, float* __restrict__ part)
{
    int g = blockIdx.x, h = blockIdx.y, b = blockIdx.z;
    __shared__ float Vt[64][64];
    __shared__ float Pt[TOPQ][64];
    int tid = threadIdx.x, w = tid >> 5, lid = tid & 31;
    float acc[5][2];
    #pragma unroll
    for (int i = 0; i < 5; i++) { acc[i][0] = 0.f; acc[i][1] = 0.f; }
    for (int t = 0; t < 8; t++) {
        int k0 = g * 512 + t * 64;
        for (int i = tid; i < 64*16; i += 256) {
            int row = i >> 4, c4 = i & 15;
            *(float4*)&Vt[row][c4*4] =
                *(const float4*)(kv + ((size_t)(b*SS + k0 + row))*(2*DD) + DD + h*DH + c4*4);
        }
        for (int i = tid; i < TOPQ*64; i += 256) {
            int q = i >> 6, kk = i & 63;
            Pt[q][kk] = pr_g[((size_t)(b*HH+h)*TOPQ + q)*SS + k0 + kk];
        }
        __syncthreads();
        int ii = 0;
        for (int q = w; q < TOPQ; q += 8, ii++) {
            float a0 = acc[ii][0], a1 = acc[ii][1];
            #pragma unroll 8
            for (int kk = 0; kk < 64; kk++) {
                float2 v = *(float2*)&Vt[kk][2*lid];
                float pp = Pt[q][kk];
                a0 = fmaf(pp, v.x, a0); a1 = fmaf(pp, v.y, a1);
            }
            acc[ii][0] = a0; acc[ii][1] = a1;
        }
        __syncthreads();
    }
    int ii = 0;
    for (int q = w; q < TOPQ; q += 8, ii++) {
        float* dst = part + (size_t)g*(BB*TOPQ*DD) + ((size_t)(b*TOPQ+q))*DD + h*DH + 2*lid;
        *(float2*)dst = make_float2(acc[ii][0], acc[ii][1]);
    }
}

// ---------------- x2 = x + base ----------------
__global__ void addbase_kernel(const float* __restrict__ x,
        const float* __restrict__ cs, float* __restrict__ x2)
{
    size_t i = (size_t)blockIdx.x * blockDim.x + threadIdx.x;
    int col4 = (int)(i & 127);
    int row  = (int)(i >> 7);
    int b    = row >> 11;
    float4 xv = ((const float4*)x)[i];
    float4 c  = ((const float4*)cs)[b*(DD/4) + col4];
    const float r = 1.0f / SS;
    ((float4*)x2)[i] = make_float4(xv.x + c.x*r, xv.y + c.y*r, xv.z + c.z*r, xv.w + c.w*r);
}

// ---------------- scatter sparse rows ----------------
__global__ __launch_bounds__(128) void scatter_kernel(const float* __restrict__ x,
        const float* __restrict__ aout, const int* __restrict__ tidx,
        float* __restrict__ x2)
{
    int r = blockIdx.x;
    int b = r / TOPQ;
    int srow = b*SS + tidx[r];
    int t = threadIdx.x;
    float4 xv = ((const float4*)x)[(size_t)srow*(DD/4) + t];
    float4 a  = ((const float4*)aout)[(size_t)r*(DD/4) + t];
    ((float4*)x2)[(size_t)srow*(DD/4) + t] =
        make_float4(xv.x + a.x, xv.y + a.y, xv.z + a.z, xv.w + a.w);
}

// ---------------- ratio tail ----------------
__global__ void ratio_kernel(float* out, int out_size)
{
    int i = NROWS*DD + blockIdx.x*blockDim.x + threadIdx.x;
    if (i < out_size) out[i] = (float)TOPQ / (float)SS;
}

// ---------------- launch ----------------
extern "C" void kernel_launch(void* const* d_in, const int* in_sizes, int n_in,
                              void* d_out, int out_size)
{
    const float* x    = (const float*)d_in[0];
    const float* ln1g = (const float*)d_in[1];
    const float* ln1b = (const float*)d_in[2];
    const float* in_w = (const float*)d_in[3];
    const float* in_b = (const float*)d_in[4];
    const float* outw = (const float*)d_in[5];
    const float* outb = (const float*)d_in[6];
    const float* ln2g = (const float*)d_in[7];
    const float* ln2b = (const float*)d_in[8];
    const float* w1   = (const float*)d_in[9];
    const float* b1   = (const float*)d_in[10];
    const float* w2   = (const float*)d_in[11];
    const float* b2   = (const float*)d_in[12];
    float* out = (float*)d_out;

    float *xn, *x2, *kv, *cs, *csp, *sp, *qs, *ctxp, *aout, *scores;
    __half *xn16, *xn2h, *h1h, *wkv16, *w1h, *w2h;
    int *tidx;
    cudaGetSymbolAddress((void**)&xn,    g_xn);
    cudaGetSymbolAddress((void**)&x2,    g_x2);
    cudaGetSymbolAddress((void**)&kv,    g_kv);
    cudaGetSymbolAddress((void**)&cs,    g_cs);
    cudaGetSymbolAddress((void**)&csp,   g_cspart);
    cudaGetSymbolAddress((void**)&sp,    g_sp);
    cudaGetSymbolAddress((void**)&qs,    g_qs);
    cudaGetSymbolAddress((void**)&ctxp,  g_ctxp);
    cudaGetSymbolAddress((void**)&aout,  g_aout);
    cudaGetSymbolAddress((void**)&scores,g_scores);
    cudaGetSymbolAddress((void**)&tidx,  g_tidx);
    cudaGetSymbolAddress((void**)&xn16,  g_xn16);
    cudaGetSymbolAddress((void**)&xn2h,  g_xn2h);
    cudaGetSymbolAddress((void**)&h1h,   g_h1h);
    cudaGetSymbolAddress((void**)&wkv16, g_wkv16);
    cudaGetSymbolAddress((void**)&w1h,   g_w1h);
    cudaGetSymbolAddress((void**)&w2h,   g_w2h);

    // 0) weight conversions (independent; overlap with early kernels)
    f2h_kernel<<<(2*DD*DD/4 + 255)/256, 256>>>(in_w + (size_t)DD*DD, wkv16, 2*DD*DD/4);
    f2h_kernel<<<(FF_*DD/4 + 255)/256, 256>>>(w1, w1h, FF_*DD/4);
    f2h_kernel<<<(DD*FF_/4 + 255)/256, 256>>>(w2, w2h, DD*FF_/4);
    // 1) layernorm1 (fp32 + fp16 outputs)
    lnw_kernel<<<NROWS/8, 256>>>(x, ln1g, ln1b, xn, xn16);
    // 2) column sums
    colsum1_kernel<<<dim3(DD/128, BB, 16), 128>>>(xn, csp);
    colsum2_kernel<<<(BB*DD + 255)/256, 256>>>(csp, cs);
    // 3) analytic sparsity
    sparsw_kernel<<<NROWS/8, 256>>>(xn, cs, sp);
    // 4) top-39 per batch
    topk_kernel<<<BB, 256>>>(sp, tidx);
    // 5) gather + Q projection
    rowproj_kernel<<<BB*TOPQ, 256>>>(xn, tidx, nullptr, in_w, in_b, qs);
    // 6) fused K+V projection
    hgemm<0, float><<<dim3((2*DD)/128, NROWS/128), 256>>>(
        xn16, wkv16, in_b + DD, nullptr, kv, 2*DD, DD);
    // 7) attention
    scorek_kernel<<<dim3(SS/128, HH, BB), 256>>>(qs, kv, scores);
    softmax_kernel<<<BB*HH*TOPQ, 256>>>(scores);
    ctxv_kernel<<<dim3(4, HH, BB), 256>>>(scores, kv, ctxp);
    // 8) output projection (partial sum fused)
    rowproj_kernel<<<BB*TOPQ, 256>>>(nullptr, nullptr, ctxp, outw, outb, aout);
    // 9) residual
    addbase_kernel<<<(NROWS*(DD/4))/256, 256>>>(x, cs, x2);
    scatter_kernel<<<BB*TOPQ, 128>>>(x, aout, tidx, x2);
    // 10) layernorm2 (fp16 only)
    lnw_kernel<<<NROWS/8, 256>>>(x2, ln2g, ln2b, nullptr, xn2h);
    // 11) FFN
    hgemm<1, __half><<<dim3(FF_/128, NROWS/128), 256>>>(
        xn2h, w1h, b1, nullptr, h1h, FF_, DD);
    hgemm<2, float><<<dim3(DD/128, NROWS/128), 256>>>(
        h1h, w2h, b2, x2, out, DD, FF_);
    // 12) ratio tail
    if (out_size > NROWS*DD) {
        int tail = out_size - NROWS*DD;
        ratio_kernel<<<(tail + 255)/256, 256>>>(out, out_size);
    }
}

// round 6
// speedup vs baseline: 3.1550x; 1.0235x over previous
#include <cuda_runtime.h>
#include <cuda_fp16.h>
#include <math.h>
#include <stdint.h>

#define BB 8
#define SS 2048
#define DD 512
#define FF_ 2048
#define HH 8
#define DH 64
#define TOPQ 39
#define NROWS (BB*SS)   /* 16384 */

// ---------------- static scratch ----------------
__device__ float g_xn  [NROWS*DD];
__device__ float g_x2  [NROWS*DD];
__device__ float g_kv  [NROWS*2*DD];
__device__ float g_cs  [BB*DD];
__device__ float g_cspart[16*BB*DD];
__device__ float g_sp  [BB*SS];
__device__ int   g_tidx[BB*TOPQ];
__device__ float g_qs  [BB*TOPQ*DD];
__device__ float g_ctxp[4*BB*TOPQ*DD];
__device__ float g_aout[BB*TOPQ*DD];
__device__ float g_scores[(size_t)BB*HH*TOPQ*SS];
// fp16 operand copies
__device__ __half g_xn16 [NROWS*DD];
__device__ __half g_xn2h [NROWS*DD];
__device__ __half g_h1h  [(size_t)NROWS*FF_];
__device__ __half g_wkv16[2*DD*DD];
__device__ __half g_w1h  [FF_*DD];
__device__ __half g_w2h  [DD*FF_];

// ---------------- helpers ----------------
__device__ __forceinline__ uint32_t s2u(const void* p) {
    uint32_t a;
    asm("{ .reg .u64 t; cvta.to.shared.u64 t, %1; cvt.u32.u64 %0, t; }" : "=r"(a) : "l"(p));
    return a;
}
__device__ __forceinline__ void mma_f16(float* d, const uint32_t* a, const uint32_t* b) {
    asm volatile("mma.sync.aligned.m16n8k16.row.col.f32.f16.f16.f32 "
        "{%0,%1,%2,%3}, {%4,%5,%6,%7}, {%8,%9}, {%0,%1,%2,%3};"
        : "+f"(d[0]), "+f"(d[1]), "+f"(d[2]), "+f"(d[3])
        : "r"(a[0]), "r"(a[1]), "r"(a[2]), "r"(a[3]), "r"(b[0]), "r"(b[1]));
}
__device__ __forceinline__ void ldsm4(uint32_t* r, uint32_t addr) {
    asm volatile("ldmatrix.sync.aligned.m8n8.x4.shared.b16 {%0,%1,%2,%3}, [%4];"
        : "=r"(r[0]), "=r"(r[1]), "=r"(r[2]), "=r"(r[3]) : "r"(addr));
}
__device__ __forceinline__ void cpa16(uint32_t dst, const void* src) {
    asm volatile("cp.async.cg.shared.global [%0], [%1], 16;" :: "r"(dst), "l"(src));
}
__device__ __forceinline__ void cpcommit() {
    asm volatile("cp.async.commit_group;" ::: "memory");
}
template<int N> __device__ __forceinline__ void cpwait() {
    asm volatile("cp.async.wait_group %0;" :: "n"(N) : "memory");
}
__device__ __forceinline__ float gelu_f(float x) {
    return 0.5f * x * (1.0f + erff(x * 0.7071067811865476f));
}

// ====================================================================
// fp16 GEMM, fp16 operands in gmem, 4-stage cp.async pipeline.
// C[M,N] = A[M,K] @ W[N,K]^T + bias (+epi). CTA 128x128, K-chunk 32,
// 256 thr = 8 warps (2M x 4N), warp 64x32, 2 CTAs/SM, one sync/chunk.
// SMEM per stage 16KB: A(8KB)+B(8KB); row x 64B; unit u at (u ^ (row&3)).
// ====================================================================
#define HG_SMEM (4*16384)

template<int EPI, typename OutT>   // EPI: 0=none, 1=gelu, 2=+res
__global__ __launch_bounds__(256, 2) void hgemm(
    const __half* __restrict__ A, const __half* __restrict__ W,
    const float* __restrict__ bias, const float* __restrict__ res,
    OutT* __restrict__ C, int N, int K)
{
    extern __shared__ __align__(16) char smh[];
    const int tid  = threadIdx.x;
    const int lane = tid & 31;
    const int wid  = tid >> 5;
    const int wm   = wid >> 2;
    const int wn   = wid & 3;
    const int bm = blockIdx.y * 128;
    const int bn = blockIdx.x * 128;
    const uint32_t sb = s2u(smh);

    const __half* Ab = A + (size_t)bm * K;
    const __half* Wb = W + (size_t)bn * K;

    // per-thread cp.async coords (2 rows x 1 unit each, x2 for A row range)
    const int crow0 = tid >> 2;            // 0..63
    const int cunit = tid & 3;

    auto ISSUE = [&](int buf, int kbase) {
        uint32_t base = sb + buf * 16384;
        #pragma unroll
        for (int i = 0; i < 2; i++) {
            int row = crow0 + i * 64;
            uint32_t off = row*64 + ((cunit ^ (row&3))*16);
            cpa16(base + off,        Ab + (size_t)row*K + kbase + cunit*8);
            cpa16(base + 8192 + off, Wb + (size_t)row*K + kbase + cunit*8);
        }
        cpcommit();
    };

    float acc[4][4][4];
    #pragma unroll
    for (int a = 0; a < 4; a++)
        #pragma unroll
        for (int b = 0; b < 4; b++)
            #pragma unroll
            for (int c = 0; c < 4; c++) acc[a][b][c] = 0.f;

    const int nk = K >> 5;      // >= 16 always here
    const int lm = lane >> 3;
    const int lr = lane & 7;

    ISSUE(0, 0);
    ISSUE(1, 32);
    ISSUE(2, 64);

    for (int kt = 0; kt < nk; kt++) {
        cpwait<2>();                 // group kt complete
        __syncthreads();             // all warps done with chunk kt-1
        if (kt + 3 < nk) ISSUE((kt + 3) & 3, (kt + 3) << 5);
        else             cpcommit(); // empty group keeps accounting uniform

        int buf = kt & 3;
        uint32_t Abase = sb + buf*16384;
        uint32_t Bbase = Abase + 8192;
        #pragma unroll
        for (int s = 0; s < 2; s++) {
            uint32_t af[4][4];
            #pragma unroll
            for (int mt = 0; mt < 4; mt++) {
                int row = wm*64 + mt*16 + (lm&1)*8 + lr;
                int unit = s*2 + (lm>>1);
                ldsm4(af[mt], Abase + row*64 + ((unit ^ (row&3))*16));
            }
            uint32_t bf[4][2];
            #pragma unroll
            for (int np = 0; np < 2; np++) {
                int nr = wn*32 + (np*2 + (lm>>1))*8 + lr;
                int unit = s*2 + (lm&1);
                uint32_t r[4];
                ldsm4(r, Bbase + nr*64 + ((unit ^ (nr&3))*16));
                bf[np*2][0] = r[0]; bf[np*2][1] = r[1];
                bf[np*2+1][0] = r[2]; bf[np*2+1][1] = r[3];
            }
            #pragma unroll
            for (int mt = 0; mt < 4; mt++)
                #pragma unroll
                for (int nt = 0; nt < 4; nt++)
                    mma_f16(acc[mt][nt], af[mt], bf[nt]);
        }
    }

    const int g = lane >> 2, t = lane & 3;
    #pragma unroll
    for (int mt = 0; mt < 4; mt++) {
        int row0 = bm + wm*64 + mt*16 + g;
        #pragma unroll
        for (int nt = 0; nt < 4; nt++) {
            int col = bn + wn*32 + nt*8 + 2*t;
            float b0 = bias[col], b1 = bias[col+1];
            float v0 = acc[mt][nt][0] + b0;
            float v1 = acc[mt][nt][1] + b1;
            float v2 = acc[mt][nt][2] + b0;
            float v3 = acc[mt][nt][3] + b1;
            if (EPI == 1) {
                v0 = gelu_f(v0); v1 = gelu_f(v1); v2 = gelu_f(v2); v3 = gelu_f(v3);
            }
            if (EPI == 2) {
                const float* r0 = res + (size_t)row0*N + col;
                const float* r1 = res + (size_t)(row0+8)*N + col;
                v0 += r0[0]; v1 += r0[1]; v2 += r1[0]; v3 += r1[1];
            }
            if constexpr (sizeof(OutT) == 2) {
                *(__half2*)&C[(size_t)row0*N + col]     = __floats2half2_rn(v0, v1);
                *(__half2*)&C[(size_t)(row0+8)*N + col] = __floats2half2_rn(v2, v3);
            } else {
                *(float2*)&C[(size_t)row0*N + col]     = make_float2(v0, v1);
                *(float2*)&C[(size_t)(row0+8)*N + col] = make_float2(v2, v3);
            }
        }
    }
}

// ---------------- fp32 -> fp16 bulk convert ----------------
__global__ void f2h_kernel(const float* __restrict__ src, __half* __restrict__ dst, int n4)
{
    int i = blockIdx.x * 256 + threadIdx.x;
    if (i < n4) {
        float4 v = ((const float4*)src)[i];
        ((__half2*)dst)[2*i]   = __floats2half2_rn(v.x, v.y);
        ((__half2*)dst)[2*i+1] = __floats2half2_rn(v.z, v.w);
    }
}

// ---------------- layernorm: warp per row ----------------
__global__ __launch_bounds__(256) void lnw_kernel(const float* __restrict__ x,
        const float* __restrict__ g, const float* __restrict__ bb,
        float* __restrict__ out, __half* __restrict__ out16)
{
    int row  = blockIdx.x * 8 + (threadIdx.x >> 5);
    int lane = threadIdx.x & 31;
    const float4* xr = (const float4*)x + (size_t)row*(DD/4);
    float4 v[4];
    #pragma unroll
    for (int j = 0; j < 4; j++) v[j] = xr[lane + 32*j];
    float s = 0.f;
    #pragma unroll
    for (int j = 0; j < 4; j++) s += v[j].x + v[j].y + v[j].z + v[j].w;
    #pragma unroll
    for (int o = 16; o > 0; o >>= 1) s += __shfl_xor_sync(0xffffffffu, s, o);
    float mean = s * (1.0f/DD);
    float q = 0.f;
    #pragma unroll
    for (int j = 0; j < 4; j++) {
        float a = v[j].x-mean, b = v[j].y-mean, c = v[j].z-mean, d = v[j].w-mean;
        q += a*a + b*b + c*c + d*d;
    }
    #pragma unroll
    for (int o = 16; o > 0; o >>= 1) q += __shfl_xor_sync(0xffffffffu, q, o);
    float inv = rsqrtf(q * (1.0f/DD) + 1e-5f);
    #pragma unroll
    for (int j = 0; j < 4; j++) {
        float4 gg = ((const float4*)g)[lane + 32*j];
        float4 bv = ((const float4*)bb)[lane + 32*j];
        float4 o4 = make_float4(
            (v[j].x-mean)*inv*gg.x + bv.x, (v[j].y-mean)*inv*gg.y + bv.y,
            (v[j].z-mean)*inv*gg.z + bv.z, (v[j].w-mean)*inv*gg.w + bv.w);
        if (out) ((float4*)out)[(size_t)row*(DD/4) + lane + 32*j] = o4;
        if (out16) {
            int base = (int)(lane + 32*j);
            ((__half2*)(out16 + (size_t)row*DD))[2*base]   = __floats2half2_rn(o4.x, o4.y);
            ((__half2*)(out16 + (size_t)row*DD))[2*base+1] = __floats2half2_rn(o4.z, o4.w);
        }
    }
}

// ---------------- column sums, two-stage deterministic ----------------
__global__ void colsum1_kernel(const float* __restrict__ xn, float* __restrict__ part)
{
    int b = blockIdx.y;
    int c = blockIdx.z;
    int d = blockIdx.x * 128 + threadIdx.x;
    const float* p = xn + (size_t)b*SS*DD + (size_t)c*128*DD + d;
    float s = 0.f;
    #pragma unroll 8
    for (int k = 0; k < 128; k++) s += p[(size_t)k*DD];
    part[((size_t)c*BB + b)*DD + d] = s;
}
__global__ void colsum2_kernel(const float* __restrict__ part, float* __restrict__ cs)
{
    int i = blockIdx.x * 256 + threadIdx.x;
    if (i < BB*DD) {
        float s = 0.f;
        #pragma unroll
        for (int c = 0; c < 16; c++) s += part[(size_t)c*BB*DD + i];
        cs[i] = s;
    }
}

// ---------------- sparsity: warp per row ----------------
__global__ __launch_bounds__(256) void sparsw_kernel(const float* __restrict__ xn,
        const float* __restrict__ cs, float* __restrict__ sp)
{
    int row  = blockIdx.x * 8 + (threadIdx.x >> 5);
    int lane = threadIdx.x & 31;
    int b = row >> 11;
    const float4* xr = (const float4*)xn + (size_t)row*(DD/4);
    const float4* cr = (const float4*)cs + b*(DD/4);
    float dp = 0.f, de = 0.f, mp = 0.f, me = 0.f;
    #pragma unroll
    for (int j = 0; j < 4; j++) {
        float4 v = xr[lane + 32*j];
        float4 c = cr[lane + 32*j];
        float vv[4] = {v.x, v.y, v.z, v.w};
        float cc[4] = {c.x, c.y, c.z, c.w};
        #pragma unroll
        for (int e = 0; e < 4; e++) {
            float p = vv[e]*vv[e];
            de += fmaf(vv[e], vv[e], -p);
            dp += p;
            float q = vv[e]*cc[e];
            me += fmaf(vv[e], cc[e], -q);
            mp += q;
        }
    }
    double dd = (double)dp + (double)de;
    double dm = (double)mp + (double)me;
    #pragma unroll
    for (int o = 16; o > 0; o >>= 1) {
        dd += __shfl_xor_sync(0xffffffffu, dd, o);
        dm += __shfl_xor_sync(0xffffffffu, dm, o);
    }
    if (lane == 0)
        sp[row] = (float)((dd - dm * (1.0/SS)) * 0.04419417382415922);
}

// ---------------- top-39 ----------------
__global__ __launch_bounds__(256) void topk_kernel(const float* __restrict__ sp,
        int* __restrict__ tidx)
{
    int b = blockIdx.x;
    int t = threadIdx.x;
    __shared__ float sv[SS];
    __shared__ float rbv[8];
    __shared__ int   rbi[8];
    for (int i = t; i < SS; i += 256) sv[i] = sp[b*SS + i];
    __syncthreads();
    for (int sel = 0; sel < TOPQ; ++sel) {
        float bv = -3.0e38f; int bi = 0;
        for (int i = t; i < SS; i += 256) {
            float v = sv[i];
            if (v > bv || (v == bv && i < bi)) { bv = v; bi = i; }
        }
        #pragma unroll
        for (int o = 16; o > 0; o >>= 1) {
            float ov = __shfl_down_sync(0xffffffffu, bv, o);
            int   oi = __shfl_down_sync(0xffffffffu, bi, o);
            if (ov > bv || (ov == bv && oi < bi)) { bv = ov; bi = oi; }
        }
        if ((t & 31) == 0) { rbv[t >> 5] = bv; rbi[t >> 5] = bi; }
        __syncthreads();
        if (t == 0) {
            float fv = rbv[0]; int fi = rbi[0];
            #pragma unroll
            for (int w = 1; w < 8; w++)
                if (rbv[w] > fv || (rbv[w] == fv && rbi[w] < fi)) { fv = rbv[w]; fi = rbi[w]; }
            tidx[b*TOPQ + sel] = fi;
            sv[fi] = -3.4e38f;
        }
        __syncthreads();
    }
}

// ---------------- small row projection ----------------
__global__ __launch_bounds__(256) void rowproj_kernel(const float* __restrict__ src,
        const int* __restrict__ gidx, const float* __restrict__ part,
        const float* __restrict__ W, const float* __restrict__ bias,
        float* __restrict__ out)
{
    int r = blockIdx.x;
    __shared__ float xr[DD];
    if (part) {
        const int N4 = BB*TOPQ*DD/4;
        const float4* p = (const float4*)part;
        for (int i = threadIdx.x; i < DD/4; i += 256) {
            int idx = r*(DD/4) + i;
            float4 a = p[idx], b = p[idx+N4], c = p[idx+2*N4], d = p[idx+3*N4];
            ((float4*)xr)[i] = make_float4(a.x+b.x+c.x+d.x, a.y+b.y+c.y+d.y,
                                           a.z+b.z+c.z+d.z, a.w+b.w+c.w+d.w);
        }
    } else {
        const float* srow;
        if (gidx) { int b = r / TOPQ; srow = src + ((size_t)b*SS + gidx[r]) * DD; }
        else        srow = src + (size_t)r * DD;
        for (int i = threadIdx.x; i < DD/4; i += 256)
            ((float4*)xr)[i] = ((const float4*)srow)[i];
    }
    __syncthreads();
    for (int j = threadIdx.x; j < DD; j += 256) {
        const float4* w4 = (const float4*)(W + (size_t)j*DD);
        float acc = 0.f;
        #pragma unroll 4
        for (int k = 0; k < DD/4; k++) {
            float4 w = w4[k]; float4 xv = ((float4*)xr)[k];
            acc = fmaf(w.x, xv.x, fmaf(w.y, xv.y, fmaf(w.z, xv.z, fmaf(w.w, xv.w, acc))));
        }
        out[(size_t)r*DD + j] = acc + bias[j];
    }
}

// ---------------- attention: scores ----------------
__global__ __launch_bounds__(256) void scorek_kernel(const float* __restrict__ qs,
        const float* __restrict__ kv, float* __restrict__ sc)
{
    int kt = blockIdx.x, h = blockIdx.y, b = blockIdx.z;
    __shared__ float Qt[DH][TOPQ+1];
    __shared__ float Ks[128][DH];
    int tid = threadIdx.x;
    for (int i = tid; i < TOPQ*DH; i += 256) {
        int q = i % TOPQ, d = i / TOPQ;
        Qt[d][q] = qs[((size_t)(b*TOPQ+q))*DD + h*DH + d];
    }
    for (int i = tid; i < 128*16; i += 256) {
        int row = i >> 4, c4 = i & 15;
        *(float4*)&Ks[row][c4*4] =
            *(const float4*)(kv + ((size_t)(b*SS + kt*128 + row))*(2*DD) + h*DH + c4*4);
    }
    __syncthreads();
    for (int p = tid; p < TOPQ*128; p += 256) {
        int q = p % TOPQ, k = p / TOPQ;
        float a = 0.f;
        #pragma unroll 8
        for (int d = 0; d < DH; d++) a = fmaf(Qt[d][q], Ks[k][d], a);
        sc[((size_t)(b*HH+h)*TOPQ + q)*SS + kt*128 + k] = a * 0.125f;
    }
}

// ---------------- attention: row softmax ----------------
__global__ __launch_bounds__(256) void softmax_kernel(float* __restrict__ sc)
{
    size_t base = (size_t)blockIdx.x * SS;
    int t = threadIdx.x;
    float4* p = (float4*)(sc + base);
    float4 v0 = p[t], v1 = p[t + 256];
    __shared__ float red[8];
    float m = fmaxf(fmaxf(fmaxf(v0.x, v0.y), fmaxf(v0.z, v0.w)),
                    fmaxf(fmaxf(v1.x, v1.y), fmaxf(v1.z, v1.w)));
    #pragma unroll
    for (int o = 16; o > 0; o >>= 1) m = fmaxf(m, __shfl_down_sync(0xffffffffu, m, o));
    if ((t & 31) == 0) red[t >> 5] = m;
    __syncthreads();
    m = red[0];
    #pragma unroll
    for (int w = 1; w < 8; w++) m = fmaxf(m, red[w]);
    __syncthreads();
    v0.x = __expf(v0.x - m); v0.y = __expf(v0.y - m);
    v0.z = __expf(v0.z - m); v0.w = __expf(v0.w - m);
    v1.x = __expf(v1.x - m); v1.y = __expf(v1.y - m);
    v1.z = __expf(v1.z - m); v1.w = __expf(v1.w - m);
    float s = v0.x+v0.y+v0.z+v0.w + v1.x+v1.y+v1.z+v1.w;
    #pragma unroll
    for (int o = 16; o > 0; o >>= 1) s += __shfl_down_sync(0xffffffffu, s, o);
    if ((t & 31) == 0) red[t >> 5] = s;
    __syncthreads();
    float tot = red[0]+red[1]+red[2]+red[3]+red[4]+red[5]+red[6]+red[7];
    float inv = 1.0f / tot;
    v0.x*=inv; v0.y*=inv; v0.z*=inv; v0.w*=inv;
    v1.x*=inv; v1.y*=inv; v1.z*=inv; v1.w*=inv;
    p[t] = v0; p[t + 256] = v1;
}

// ---------------- attention: probs @ V ----------------
__global__ __launch_bounds__(256) void ctxv_kernel(const float* __restrict__ pr_g,
        const float* __restrict__ kv, float* __restrict__ part)
{
    int g = blockIdx.x, h = blockIdx.y, b = blockIdx.z;
    __shared__ float Vt[64][64];
    __shared__ float Pt[TOPQ][64];
    int tid = threadIdx.x, w = tid >> 5, lid = tid & 31;
    float acc[5][2];
    #pragma unroll
    for (int i = 0; i < 5; i++) { acc[i][0] = 0.f; acc[i][1] = 0.f; }
    for (int t = 0; t < 8; t++) {
        int k0 = g * 512 + t * 64;
        for (int i = tid; i < 64*16; i += 256) {
            int row = i >> 4, c4 = i & 15;
            *(float4*)&Vt[row][c4*4] =
                *(const float4*)(kv + ((size_t)(b*SS + k0 + row))*(2*DD) + DD + h*DH + c4*4);
        }
        for (int i = tid; i < TOPQ*64; i += 256) {
            int q = i >> 6, kk = i & 63;
            Pt[q][kk] = pr_g[((size_t)(b*HH+h)*TOPQ + q)*SS + k0 + kk];
        }
        __syncthreads();
        int ii = 0;
        for (int q = w; q < TOPQ; q += 8, ii++) {
            float a0 = acc[ii][0], a1 = acc[ii][1];
            #pragma unroll 8
            for (int kk = 0; kk < 64; kk++) {
                float2 v = *(float2*)&Vt[kk][2*lid];
                float pp = Pt[q][kk];
                a0 = fmaf(pp, v.x, a0); a1 = fmaf(pp, v.y, a1);
            }
            acc[ii][0] = a0; acc[ii][1] = a1;
        }
        __syncthreads();
    }
    int ii = 0;
    for (int q = w; q < TOPQ; q += 8, ii++) {
        float* dst = part + (size_t)g*(BB*TOPQ*DD) + ((size_t)(b*TOPQ+q))*DD + h*DH + 2*lid;
        *(float2*)dst = make_float2(acc[ii][0], acc[ii][1]);
    }
}

// ---------------- x2 = x + base ----------------
__global__ void addbase_kernel(const float* __restrict__ x,
        const float* __restrict__ cs, float* __restrict__ x2)
{
    size_t i = (size_t)blockIdx.x * blockDim.x + threadIdx.x;
    int col4 = (int)(i & 127);
    int row  = (int)(i >> 7);
    int b    = row >> 11;
    float4 xv = ((const float4*)x)[i];
    float4 c  = ((const float4*)cs)[b*(DD/4) + col4];
    const float r = 1.0f / SS;
    ((float4*)x2)[i] = make_float4(xv.x + c.x*r, xv.y + c.y*r, xv.z + c.z*r, xv.w + c.w*r);
}

// ---------------- scatter sparse rows ----------------
__global__ __launch_bounds__(128) void scatter_kernel(const float* __restrict__ x,
        const float* __restrict__ aout, const int* __restrict__ tidx,
        float* __restrict__ x2)
{
    int r = blockIdx.x;
    int b = r / TOPQ;
    int srow = b*SS + tidx[r];
    int t = threadIdx.x;
    float4 xv = ((const float4*)x)[(size_t)srow*(DD/4) + t];
    float4 a  = ((const float4*)aout)[(size_t)r*(DD/4) + t];
    ((float4*)x2)[(size_t)srow*(DD/4) + t] =
        make_float4(xv.x + a.x, xv.y + a.y, xv.z + a.z, xv.w + a.w);
}

// ---------------- ratio tail ----------------
__global__ void ratio_kernel(float* out, int out_size)
{
    int i = NROWS*DD + blockIdx.x*blockDim.x + threadIdx.x;
    if (i < out_size) out[i] = (float)TOPQ / (float)SS;
}

// ---------------- launch ----------------
extern "C" void kernel_launch(void* const* d_in, const int* in_sizes, int n_in,
                              void* d_out, int out_size)
{
    const float* x    = (const float*)d_in[0];
    const float* ln1g = (const float*)d_in[1];
    const float* ln1b = (const float*)d_in[2];
    const float* in_w = (const float*)d_in[3];
    const float* in_b = (const float*)d_in[4];
    const float* outw = (const float*)d_in[5];
    const float* outb = (const float*)d_in[6];
    const float* ln2g = (const float*)d_in[7];
    const float* ln2b = (const float*)d_in[8];
    const float* w1   = (const float*)d_in[9];
    const float* b1   = (const float*)d_in[10];
    const float* w2   = (const float*)d_in[11];
    const float* b2   = (const float*)d_in[12];
    float* out = (float*)d_out;

    float *xn, *x2, *kv, *cs, *csp, *sp, *qs, *ctxp, *aout, *scores;
    __half *xn16, *xn2h, *h1h, *wkv16, *w1h, *w2h;
    int *tidx;
    cudaGetSymbolAddress((void**)&xn,    g_xn);
    cudaGetSymbolAddress((void**)&x2,    g_x2);
    cudaGetSymbolAddress((void**)&kv,    g_kv);
    cudaGetSymbolAddress((void**)&cs,    g_cs);
    cudaGetSymbolAddress((void**)&csp,   g_cspart);
    cudaGetSymbolAddress((void**)&sp,    g_sp);
    cudaGetSymbolAddress((void**)&qs,    g_qs);
    cudaGetSymbolAddress((void**)&ctxp,  g_ctxp);
    cudaGetSymbolAddress((void**)&aout,  g_aout);
    cudaGetSymbolAddress((void**)&scores,g_scores);
    cudaGetSymbolAddress((void**)&tidx,  g_tidx);
    cudaGetSymbolAddress((void**)&xn16,  g_xn16);
    cudaGetSymbolAddress((void**)&xn2h,  g_xn2h);
    cudaGetSymbolAddress((void**)&h1h,   g_h1h);
    cudaGetSymbolAddress((void**)&wkv16, g_wkv16);
    cudaGetSymbolAddress((void**)&w1h,   g_w1h);
    cudaGetSymbolAddress((void**)&w2h,   g_w2h);

    cudaFuncSetAttribute(hgemm<0, float>,  cudaFuncAttributeMaxDynamicSharedMemorySize, HG_SMEM);
    cudaFuncSetAttribute(hgemm<1, __half>, cudaFuncAttributeMaxDynamicSharedMemorySize, HG_SMEM);
    cudaFuncSetAttribute(hgemm<2, float>,  cudaFuncAttributeMaxDynamicSharedMemorySize, HG_SMEM);

    // 0) weight conversions
    f2h_kernel<<<(2*DD*DD/4 + 255)/256, 256>>>(in_w + (size_t)DD*DD, wkv16, 2*DD*DD/4);
    f2h_kernel<<<(FF_*DD/4 + 255)/256, 256>>>(w1, w1h, FF_*DD/4);
    f2h_kernel<<<(DD*FF_/4 + 255)/256, 256>>>(w2, w2h, DD*FF_/4);
    // 1) layernorm1 (fp32 + fp16 outputs)
    lnw_kernel<<<NROWS/8, 256>>>(x, ln1g, ln1b, xn, xn16);
    // 2) column sums
    colsum1_kernel<<<dim3(DD/128, BB, 16), 128>>>(xn, csp);
    colsum2_kernel<<<(BB*DD + 255)/256, 256>>>(csp, cs);
    // 3) analytic sparsity
    sparsw_kernel<<<NROWS/8, 256>>>(xn, cs, sp);
    // 4) top-39 per batch
    topk_kernel<<<BB, 256>>>(sp, tidx);
    // 5) gather + Q projection
    rowproj_kernel<<<BB*TOPQ, 256>>>(xn, tidx, nullptr, in_w, in_b, qs);
    // 6) fused K+V projection
    hgemm<0, float><<<dim3((2*DD)/128, NROWS/128), 256, HG_SMEM>>>(
        xn16, wkv16, in_b + DD, nullptr, kv, 2*DD, DD);
    // 7) attention
    scorek_kernel<<<dim3(SS/128, HH, BB), 256>>>(qs, kv, scores);
    softmax_kernel<<<BB*HH*TOPQ, 256>>>(scores);
    ctxv_kernel<<<dim3(4, HH, BB), 256>>>(scores, kv, ctxp);
    // 8) output projection (partial sum fused)
    rowproj_kernel<<<BB*TOPQ, 256>>>(nullptr, nullptr, ctxp, outw, outb, aout);
    // 9) residual
    addbase_kernel<<<(NROWS*(DD/4))/256, 256>>>(x, cs, x2);
    scatter_kernel<<<BB*TOPQ, 128>>>(x, aout, tidx, x2);
    // 10) layernorm2 (fp16 only)
    lnw_kernel<<<NROWS/8, 256>>>(x2, ln2g, ln2b, nullptr, xn2h);
    // 11) FFN
    hgemm<1, __half><<<dim3(FF_/128, NROWS/128), 256, HG_SMEM>>>(
        xn2h, w1h, b1, nullptr, h1h, FF_, DD);
    hgemm<2, float><<<dim3(DD/128, NROWS/128), 256, HG_SMEM>>>(
        h1h, w2h, b2, x2, out, DD, FF_);
    // 12) ratio tail
    if (out_size > NROWS*DD) {
        int tail = out_size - NROWS*DD;
        ratio_kernel<<<(tail + 255)/256, 256>>>(out, out_size);
    }
}